// round 14
// baseline (speedup 1.0000x reference)
#include <cuda_runtime.h>
#include <cstdint>

#define NDRUG 100000
#define NPROT 50000
#define EDD 800000
#define EDP 600000
#define EPD 600000
#define DD 128
#define XTS 68

// chunked scan geometry
#define CH 4096
#define NCH_DD 25
#define NCH_PD 25
#define NCH_DP 13
#define NCH_TOT (NCH_DD + NCH_PD + NCH_DP)   // 63

// drug pipeline split (64-row aligned)
#define DRUG_HALF 50048

typedef unsigned long long u64;

__device__ __forceinline__ u64 pk2(float lo, float hi) {
    u64 r; asm("mov.b64 %0,{%1,%2};" : "=l"(r) : "f"(lo), "f"(hi)); return r;
}
__device__ __forceinline__ u64 dp2(float v) {
    u64 r; asm("mov.b64 %0,{%1,%1};" : "=l"(r) : "f"(v)); return r;
}
__device__ __forceinline__ void fma2(u64& d, u64 a, u64 b) {
    asm("fma.rn.f32x2 %0,%1,%2,%3;" : "=l"(d) : "l"(a), "l"(b), "l"(d));
}
__device__ __forceinline__ void up2(u64 v, float& lo, float& hi) {
    asm("mov.b64 {%0,%1},%2;" : "=f"(lo), "=f"(hi) : "l"(v));
}

// ---------------- scratch ----------------
__device__ __align__(16) float g_Hdd[(size_t)NDRUG * DD];
__device__ __align__(16) float g_Hdp[(size_t)NDRUG * DD];
__device__ __align__(16) float g_Hpd[(size_t)NPROT * DD];
__device__ __align__(16) float g_Adrug[(size_t)NDRUG * DD];
__device__ __align__(16) float g_Aprot[(size_t)NPROT * DD];
// CSR
__device__ __align__(16) int g_cnt_dd[NDRUG];
__device__ __align__(16) int g_cnt_pd[NDRUG];
__device__ __align__(16) int g_cnt_dp[NPROT];
__device__ __align__(16) int g_off_dd[NDRUG + 4];
__device__ __align__(16) int g_off_pd[NDRUG + 4];
__device__ __align__(16) int g_off_dp[NPROT + 4];
__device__ __align__(16) int g_cur_dd[NDRUG + 4];
__device__ __align__(16) int g_cur_pd[NDRUG + 4];
__device__ __align__(16) int g_cur_dp[NPROT + 4];
__device__ int g_esrc_dd[EDD];
__device__ int g_esrc_pd[EPD];
__device__ int g_esrc_dp[EDP];
__device__ int g_part[NCH_TOT];
__device__ int g_pbase[NCH_TOT];
// transposed weights
__device__ __align__(16) float g_WtDD[DD * DD];
__device__ __align__(16) float g_WtDP[DD * DD];
__device__ __align__(16) float g_WtPD[DD * DD];
__device__ __align__(16) float g_WtDR[DD * 2 * DD];
__device__ __align__(16) float g_WtPR[DD * 2 * DD];

// ---------------- host-side stream/event resources ----------------
struct GpuRes {
    cudaStream_t s1, s2;
    cudaEvent_t eFork, ePrep, eDD, ePD, eFill, eG0, eG1, eEnd2;
    GpuRes() {
        cudaStreamCreateWithFlags(&s1, cudaStreamNonBlocking);
        cudaStreamCreateWithFlags(&s2, cudaStreamNonBlocking);
        cudaEventCreateWithFlags(&eFork, cudaEventDisableTiming);
        cudaEventCreateWithFlags(&ePrep, cudaEventDisableTiming);
        cudaEventCreateWithFlags(&eDD,   cudaEventDisableTiming);
        cudaEventCreateWithFlags(&ePD,   cudaEventDisableTiming);
        cudaEventCreateWithFlags(&eFill, cudaEventDisableTiming);
        cudaEventCreateWithFlags(&eG0,   cudaEventDisableTiming);
        cudaEventCreateWithFlags(&eG1,   cudaEventDisableTiming);
        cudaEventCreateWithFlags(&eEnd2, cudaEventDisableTiming);
    }
};
static GpuRes g_res;

// ---------------- weight transpose ----------------
__global__ void prep_weights(const float* __restrict__ Wdd, const float* __restrict__ Wdp,
                             const float* __restrict__ Wpd, const float* __restrict__ Wdr,
                             const float* __restrict__ Wpr)
{
    int t = blockIdx.x * blockDim.x + threadIdx.x;
    int stride = gridDim.x * blockDim.x;
    for (int i = t; i < DD * DD; i += stride) {
        int c = i >> 7, k = i & 127;
        g_WtDD[k * DD + c] = Wdd[i];
        g_WtDP[k * DD + c] = Wdp[i];
        g_WtPD[k * DD + c] = Wpd[i];
    }
    for (int i = t; i < DD * 2 * DD; i += stride) {
        int c = i >> 8, col = i & 255;
        int k = col & 127, half = col >> 7;
        g_WtDR[k * 256 + half * 128 + c] = Wdr[i];
        g_WtPR[k * 256 + half * 128 + c] = Wpr[i];
    }
}

// ---------------- CSR build ----------------
__global__ void zero_counts() {
    int t = blockIdx.x * blockDim.x + threadIdx.x;
    int stride = gridDim.x * blockDim.x;
    for (int i = t; i < NDRUG; i += stride) { g_cnt_dd[i] = 0; g_cnt_pd[i] = 0; }
    for (int i = t; i < NPROT; i += stride) g_cnt_dp[i] = 0;
}

__global__ void count_all(const int* __restrict__ dd, const int* __restrict__ pd,
                          const int* __restrict__ dp) {
    int t = blockIdx.x * blockDim.x + threadIdx.x;
    if (t < EDD) atomicAdd(&g_cnt_dd[__ldg(&dd[t])], 1);
    else if (t < EDD + EPD) atomicAdd(&g_cnt_pd[__ldg(&pd[t - EDD])], 1);
    else if (t < EDD + EPD + EDP) atomicAdd(&g_cnt_dp[__ldg(&dp[t - EDD - EPD])], 1);
}

__device__ __forceinline__ void chunk_map(int b, const int*& cnt, int*& offs, int*& cur,
                                          int& base, int& n) {
    if (b < NCH_DD)              { cnt = g_cnt_dd; offs = g_off_dd; cur = g_cur_dd; base = b * CH; n = NDRUG; }
    else if (b < NCH_DD + NCH_PD){ cnt = g_cnt_pd; offs = g_off_pd; cur = g_cur_pd; base = (b - NCH_DD) * CH; n = NDRUG; }
    else                         { cnt = g_cnt_dp; offs = g_off_dp; cur = g_cur_dp; base = (b - NCH_DD - NCH_PD) * CH; n = NPROT; }
}

__global__ __launch_bounds__(1024) void chunk_sums() {
    const int* cnt; int* offs; int* cur; int base, n;
    chunk_map(blockIdx.x, cnt, offs, cur, base, n);
    int i0 = base + threadIdx.x * 4;
    int4 c = make_int4(0, 0, 0, 0);
    if (i0 < n) c = *reinterpret_cast<const int4*>(&cnt[i0]);
    int tot = c.x + c.y + c.z + c.w;
    __shared__ int ws[32];
    int lane = threadIdx.x & 31, wid = threadIdx.x >> 5;
#pragma unroll
    for (int o = 16; o; o >>= 1) tot += __shfl_xor_sync(0xFFFFFFFFu, tot, o);
    if (lane == 0) ws[wid] = tot;
    __syncthreads();
    if (wid == 0) {
        int v = ws[lane];
#pragma unroll
        for (int o = 16; o; o >>= 1) v += __shfl_xor_sync(0xFFFFFFFFu, v, o);
        if (lane == 0) g_part[blockIdx.x] = v;
    }
}

__global__ void scan_partials() {
    __shared__ int s[64];
    int t = threadIdx.x;
    int v = (t < NCH_TOT) ? g_part[t] : 0;
    s[t] = v;
    __syncthreads();
#pragma unroll
    for (int o = 1; o < 64; o <<= 1) {
        int add = (t >= o) ? s[t - o] : 0;
        __syncthreads();
        s[t] += add;
        __syncthreads();
    }
    if (t < NCH_TOT) {
        int excl = s[t] - v;
        int segoff = (t >= NCH_DD + NCH_PD) ? (EDD + EPD) : (t >= NCH_DD ? EDD : 0);
        g_pbase[t] = excl - segoff;
    }
    if (t == 0) {
        g_off_dd[NDRUG] = EDD;
        g_off_pd[NDRUG] = EPD;
        g_off_dp[NPROT] = EDP;
    }
}

__global__ __launch_bounds__(1024) void chunk_scan() {
    const int* cnt; int* offs; int* cur; int base, n;
    chunk_map(blockIdx.x, cnt, offs, cur, base, n);
    int carry = g_pbase[blockIdx.x];
    __shared__ int wsum[32];
    int tid = threadIdx.x, lane = tid & 31, wid = tid >> 5;
    int i0 = base + tid * 4;
    int4 c = make_int4(0, 0, 0, 0);
    if (i0 < n) c = *reinterpret_cast<const int4*>(&cnt[i0]);
    int tot = c.x + c.y + c.z + c.w;
    int incl = tot;
#pragma unroll
    for (int o = 1; o < 32; o <<= 1) {
        int v = __shfl_up_sync(0xFFFFFFFFu, incl, o);
        if (lane >= o) incl += v;
    }
    if (lane == 31) wsum[wid] = incl;
    __syncthreads();
    if (wid == 0) {
        int v = wsum[lane];
        int wincl = v;
#pragma unroll
        for (int o = 1; o < 32; o <<= 1) {
            int t2 = __shfl_up_sync(0xFFFFFFFFu, wincl, o);
            if (lane >= o) wincl += t2;
        }
        wsum[lane] = wincl - v;
    }
    __syncthreads();
    int excl = carry + wsum[wid] + incl - tot;
    if (i0 < n) {
        int e0 = excl, e1 = e0 + c.x, e2 = e1 + c.y, e3 = e2 + c.z;
        *reinterpret_cast<int4*>(&offs[i0]) = make_int4(e0, e1, e2, e3);
        *reinterpret_cast<int4*>(&cur[i0])  = make_int4(e0, e1, e2, e3);
    }
}

__global__ void fill_all(const int* __restrict__ dd_s, const int* __restrict__ dd_d,
                         const int* __restrict__ pd_s, const int* __restrict__ pd_d,
                         const int* __restrict__ dp_s, const int* __restrict__ dp_d) {
    int t = blockIdx.x * blockDim.x + threadIdx.x;
    if (t < EDD) {
        int slot = atomicAdd(&g_cur_dd[__ldg(&dd_d[t])], 1);
        g_esrc_dd[slot] = __ldg(&dd_s[t]);
    } else if (t < EDD + EPD) {
        int e = t - EDD;
        int slot = atomicAdd(&g_cur_pd[__ldg(&pd_d[e])], 1);
        g_esrc_pd[slot] = __ldg(&pd_s[e]);
    } else if (t < EDD + EPD + EDP) {
        int e = t - EDD - EPD;
        int slot = atomicAdd(&g_cur_dp[__ldg(&dp_d[e])], 1);
        g_esrc_dp[slot] = __ldg(&dp_s[e]);
    }
}

// ---------------- GEMM + ReLU (proven version) ----------------
__global__ __launch_bounds__(256, 3) void agg_gemm_relu(
    const float* __restrict__ X, const float* __restrict__ Wt,
    float* __restrict__ H, int N)
{
    __shared__ float xt[DD * XTS];

    int tid = threadIdx.x;
    int row0 = blockIdx.x * 64;
    for (int j = tid; j < 64 * 32; j += 256) {
        int r = j & 63, qg = j >> 6;
        int row = row0 + r;
        float4 v = make_float4(0.f, 0.f, 0.f, 0.f);
        if (row < N) v = *reinterpret_cast<const float4*>(&X[(size_t)row * DD + qg * 4]);
        xt[(qg * 4 + 0) * XTS + r] = v.x;
        xt[(qg * 4 + 1) * XTS + r] = v.y;
        xt[(qg * 4 + 2) * XTS + r] = v.z;
        xt[(qg * 4 + 3) * XTS + r] = v.w;
    }
    __syncthreads();

    int ct = tid & 31, rt = tid >> 5;
    int c0 = ct * 4, r0 = rt * 8;
    u64 acc[4][4];
#pragma unroll
    for (int rp = 0; rp < 4; rp++)
#pragma unroll
        for (int c = 0; c < 4; c++) acc[rp][c] = 0ull;

#pragma unroll 4
    for (int k = 0; k < DD; k++) {
        float4 w = __ldg(reinterpret_cast<const float4*>(&Wt[k * DD + c0]));
        float4 xa = *reinterpret_cast<const float4*>(&xt[k * XTS + r0]);
        float4 xb = *reinterpret_cast<const float4*>(&xt[k * XTS + r0 + 4]);
        u64 xp[4] = {pk2(xa.x, xa.y), pk2(xa.z, xa.w), pk2(xb.x, xb.y), pk2(xb.z, xb.w)};
        u64 wd[4] = {dp2(w.x), dp2(w.y), dp2(w.z), dp2(w.w)};
#pragma unroll
        for (int rp = 0; rp < 4; rp++)
#pragma unroll
            for (int c = 0; c < 4; c++) fma2(acc[rp][c], xp[rp], wd[c]);
    }

#pragma unroll
    for (int rp = 0; rp < 4; rp++) {
        float lo[4], hi[4];
#pragma unroll
        for (int c = 0; c < 4; c++) up2(acc[rp][c], lo[c], hi[c]);
        int ra = row0 + r0 + 2 * rp;
        if (ra < N) {
            float4 o = make_float4(fmaxf(lo[0], 0.f), fmaxf(lo[1], 0.f),
                                   fmaxf(lo[2], 0.f), fmaxf(lo[3], 0.f));
            *reinterpret_cast<float4*>(&H[(size_t)ra * DD + c0]) = o;
        }
        if (ra + 1 < N) {
            float4 o = make_float4(fmaxf(hi[0], 0.f), fmaxf(hi[1], 0.f),
                                   fmaxf(hi[2], 0.f), fmaxf(hi[3], 0.f));
            *reinterpret_cast<float4*>(&H[(size_t)(ra + 1) * DD + c0]) = o;
        }
    }
}

// ---------------- fused drug gather over [rb, re): A = 0.5*(mean_dd + mean_pd) ----------------
__global__ __launch_bounds__(256) void gather_drug(
    const float* __restrict__ Hdd, const float* __restrict__ Hpd,
    const int* __restrict__ esrc_dd, const int* __restrict__ off_dd,
    const int* __restrict__ esrc_pd, const int* __restrict__ off_pd,
    float* __restrict__ A, int rb, int re)
{
    int w = rb + ((blockIdx.x * blockDim.x + threadIdx.x) >> 5);
    if (w >= re) return;
    int lane = threadIdx.x & 31;
    float4 o = make_float4(0.f, 0.f, 0.f, 0.f);
#pragma unroll
    for (int rel = 0; rel < 2; rel++) {
        const float* H = rel ? Hpd : Hdd;
        const int* esrc = rel ? esrc_pd : esrc_dd;
        const int* offs = rel ? off_pd : off_dd;
        int beg = __ldg(&offs[w]), end = __ldg(&offs[w + 1]);
        float4 acc = make_float4(0.f, 0.f, 0.f, 0.f);
        int e = beg;
        for (; e + 4 <= end; e += 4) {
            int s0 = __ldg(&esrc[e]);
            int s1 = __ldg(&esrc[e + 1]);
            int s2 = __ldg(&esrc[e + 2]);
            int s3 = __ldg(&esrc[e + 3]);
            float4 v0 = __ldg(reinterpret_cast<const float4*>(&H[(size_t)s0 * DD + lane * 4]));
            float4 v1 = __ldg(reinterpret_cast<const float4*>(&H[(size_t)s1 * DD + lane * 4]));
            float4 v2 = __ldg(reinterpret_cast<const float4*>(&H[(size_t)s2 * DD + lane * 4]));
            float4 v3 = __ldg(reinterpret_cast<const float4*>(&H[(size_t)s3 * DD + lane * 4]));
            acc.x += (v0.x + v1.x) + (v2.x + v3.x);
            acc.y += (v0.y + v1.y) + (v2.y + v3.y);
            acc.z += (v0.z + v1.z) + (v2.z + v3.z);
            acc.w += (v0.w + v1.w) + (v2.w + v3.w);
        }
        for (; e < end; e++) {
            int s = __ldg(&esrc[e]);
            float4 v = __ldg(reinterpret_cast<const float4*>(&H[(size_t)s * DD + lane * 4]));
            acc.x += v.x; acc.y += v.y; acc.z += v.z; acc.w += v.w;
        }
        float inv = 0.5f / fmaxf((float)(end - beg), 1.0f);
        o.x += acc.x * inv; o.y += acc.y * inv; o.z += acc.z * inv; o.w += acc.w * inv;
    }
    *reinterpret_cast<float4*>(&A[(size_t)w * DD + lane * 4]) = o;
}

// ---------------- prot gather (single relation, direct mean) ----------------
__global__ __launch_bounds__(256) void gather_prot(
    const float* __restrict__ H, const int* __restrict__ esrc,
    const int* __restrict__ offs, float* __restrict__ A, int N)
{
    int w = (blockIdx.x * blockDim.x + threadIdx.x) >> 5;
    if (w >= N) return;
    int lane = threadIdx.x & 31;
    int beg = __ldg(&offs[w]), end = __ldg(&offs[w + 1]);
    float4 acc = make_float4(0.f, 0.f, 0.f, 0.f);
    int e = beg;
    for (; e + 4 <= end; e += 4) {
        int s0 = __ldg(&esrc[e]);
        int s1 = __ldg(&esrc[e + 1]);
        int s2 = __ldg(&esrc[e + 2]);
        int s3 = __ldg(&esrc[e + 3]);
        float4 v0 = __ldg(reinterpret_cast<const float4*>(&H[(size_t)s0 * DD + lane * 4]));
        float4 v1 = __ldg(reinterpret_cast<const float4*>(&H[(size_t)s1 * DD + lane * 4]));
        float4 v2 = __ldg(reinterpret_cast<const float4*>(&H[(size_t)s2 * DD + lane * 4]));
        float4 v3 = __ldg(reinterpret_cast<const float4*>(&H[(size_t)s3 * DD + lane * 4]));
        acc.x += (v0.x + v1.x) + (v2.x + v3.x);
        acc.y += (v0.y + v1.y) + (v2.y + v3.y);
        acc.z += (v0.z + v1.z) + (v2.z + v3.z);
        acc.w += (v0.w + v1.w) + (v2.w + v3.w);
    }
    for (; e < end; e++) {
        int s = __ldg(&esrc[e]);
        float4 v = __ldg(reinterpret_cast<const float4*>(&H[(size_t)s * DD + lane * 4]));
        acc.x += v.x; acc.y += v.y; acc.z += v.z; acc.w += v.w;
    }
    float inv = 1.0f / fmaxf((float)(end - beg), 1.0f);
    *reinterpret_cast<float4*>(&A[(size_t)w * DD + lane * 4]) =
        make_float4(acc.x * inv, acc.y * inv, acc.z * inv, acc.w * inv);
}

// ---------------- fused node update over [rb, re) ----------------
__global__ __launch_bounds__(256, 2) void node_update(
    const float* __restrict__ X,
    const float* __restrict__ A,
    const float* __restrict__ Wt,
    const float* __restrict__ b,
    const float* __restrict__ g,
    const float* __restrict__ be,
    float* __restrict__ out, int rb, int re)
{
    __shared__ float xt[DD * XTS];
    __shared__ float at[DD * XTS];

    int tid = threadIdx.x;
    int row0 = rb + blockIdx.x * 64;
    for (int j = tid; j < 64 * 32; j += 256) {
        int r = j & 63, qg = j >> 6;
        int row = row0 + r;
        float4 xv = make_float4(0.f, 0.f, 0.f, 0.f);
        float4 av = make_float4(0.f, 0.f, 0.f, 0.f);
        if (row < re) {
            xv = *reinterpret_cast<const float4*>(&X[(size_t)row * DD + qg * 4]);
            av = *reinterpret_cast<const float4*>(&A[(size_t)row * DD + qg * 4]);
        }
        xt[(qg * 4 + 0) * XTS + r] = xv.x;
        xt[(qg * 4 + 1) * XTS + r] = xv.y;
        xt[(qg * 4 + 2) * XTS + r] = xv.z;
        xt[(qg * 4 + 3) * XTS + r] = xv.w;
        at[(qg * 4 + 0) * XTS + r] = av.x;
        at[(qg * 4 + 1) * XTS + r] = av.y;
        at[(qg * 4 + 2) * XTS + r] = av.z;
        at[(qg * 4 + 3) * XTS + r] = av.w;
    }
    __syncthreads();

    int ct = tid & 31, rt = tid >> 5;
    int c0 = ct * 4, r0 = rt * 8;
    u64 acc[4][4];
#pragma unroll
    for (int rp = 0; rp < 4; rp++)
#pragma unroll
        for (int c = 0; c < 4; c++) acc[rp][c] = 0ull;

#pragma unroll 2
    for (int k = 0; k < DD; k++) {
        float4 w1 = __ldg(reinterpret_cast<const float4*>(&Wt[k * 256 + c0]));
        float4 w2 = __ldg(reinterpret_cast<const float4*>(&Wt[k * 256 + 128 + c0]));
        float4 xa = *reinterpret_cast<const float4*>(&xt[k * XTS + r0]);
        float4 xb = *reinterpret_cast<const float4*>(&xt[k * XTS + r0 + 4]);
        float4 aa = *reinterpret_cast<const float4*>(&at[k * XTS + r0]);
        float4 ab = *reinterpret_cast<const float4*>(&at[k * XTS + r0 + 4]);
        u64 xp[4] = {pk2(xa.x, xa.y), pk2(xa.z, xa.w), pk2(xb.x, xb.y), pk2(xb.z, xb.w)};
        u64 ap[4] = {pk2(aa.x, aa.y), pk2(aa.z, aa.w), pk2(ab.x, ab.y), pk2(ab.z, ab.w)};
        u64 w1d[4] = {dp2(w1.x), dp2(w1.y), dp2(w1.z), dp2(w1.w)};
        u64 w2d[4] = {dp2(w2.x), dp2(w2.y), dp2(w2.z), dp2(w2.w)};
#pragma unroll
        for (int rp = 0; rp < 4; rp++)
#pragma unroll
            for (int c = 0; c < 4; c++) {
                fma2(acc[rp][c], xp[rp], w1d[c]);
                fma2(acc[rp][c], ap[rp], w2d[c]);
            }
    }
    float4 bb = *reinterpret_cast<const float4*>(&b[c0]);
    __syncthreads();
    float* hs = xt;

#pragma unroll
    for (int rp = 0; rp < 4; rp++) {
        float lo[4], hi[4];
#pragma unroll
        for (int c = 0; c < 4; c++) up2(acc[rp][c], lo[c], hi[c]);
        int rla = r0 + 2 * rp;
        int ra = row0 + rla;
        float4 xra = make_float4(0.f, 0.f, 0.f, 0.f);
        float4 xrb = make_float4(0.f, 0.f, 0.f, 0.f);
        if (ra < re)     xra = *reinterpret_cast<const float4*>(&X[(size_t)ra * DD + c0]);
        if (ra + 1 < re) xrb = *reinterpret_cast<const float4*>(&X[(size_t)(ra + 1) * DD + c0]);
        float4 oa, ob;
        oa.x = fmaxf(lo[0] + bb.x, 0.f) + xra.x;
        oa.y = fmaxf(lo[1] + bb.y, 0.f) + xra.y;
        oa.z = fmaxf(lo[2] + bb.z, 0.f) + xra.z;
        oa.w = fmaxf(lo[3] + bb.w, 0.f) + xra.w;
        ob.x = fmaxf(hi[0] + bb.x, 0.f) + xrb.x;
        ob.y = fmaxf(hi[1] + bb.y, 0.f) + xrb.y;
        ob.z = fmaxf(hi[2] + bb.z, 0.f) + xrb.z;
        ob.w = fmaxf(hi[3] + bb.w, 0.f) + xrb.w;
        *reinterpret_cast<float4*>(&hs[rla * DD + c0]) = oa;
        *reinterpret_cast<float4*>(&hs[(rla + 1) * DD + c0]) = ob;
    }
    __syncthreads();

    int lane = tid & 31;
    float4 gg  = *reinterpret_cast<const float4*>(&g[lane * 4]);
    float4 bev = *reinterpret_cast<const float4*>(&be[lane * 4]);
    for (int r = 0; r < 8; r++) {
        int rl = rt * 8 + r;
        int row = row0 + rl;
        float4 v = *reinterpret_cast<const float4*>(&hs[rl * DD + lane * 4]);
        float s  = v.x + v.y + v.z + v.w;
        float s2 = v.x * v.x + v.y * v.y + v.z * v.z + v.w * v.w;
#pragma unroll
        for (int o_ = 16; o_; o_ >>= 1) {
            s  += __shfl_xor_sync(0xFFFFFFFFu, s, o_);
            s2 += __shfl_xor_sync(0xFFFFFFFFu, s2, o_);
        }
        float mu  = s * (1.0f / 128.0f);
        float var = s2 * (1.0f / 128.0f) - mu * mu;
        float rstd = rsqrtf(var + 1e-5f);
        if (row < re) {
            float4 o;
            o.x = (v.x - mu) * rstd * gg.x + bev.x;
            o.y = (v.y - mu) * rstd * gg.y + bev.y;
            o.z = (v.z - mu) * rstd * gg.z + bev.z;
            o.w = (v.w - mu) * rstd * gg.w + bev.w;
            *reinterpret_cast<float4*>(&out[(size_t)row * DD + lane * 4]) = o;
        }
    }
}

// ---------------- launch: R12 DAG + chunked gather/node pipeline on drug ----------------
extern "C" void kernel_launch(void* const* d_in, const int* in_sizes, int n_in,
                              void* d_out, int out_size)
{
    const float* x_drug  = (const float*)d_in[0];
    const float* x_prot  = (const float*)d_in[1];
    const float* Wagg_dd = (const float*)d_in[2];
    const float* Wagg_dp = (const float*)d_in[3];
    const float* Wagg_pd = (const float*)d_in[4];
    const float* W_drug  = (const float*)d_in[5];
    const float* b_drug  = (const float*)d_in[6];
    const float* W_prot  = (const float*)d_in[7];
    const float* b_prot  = (const float*)d_in[8];
    const float* g_drug  = (const float*)d_in[9];
    const float* be_drug = (const float*)d_in[10];
    const float* g_prot  = (const float*)d_in[11];
    const float* be_prot = (const float*)d_in[12];
    const int* dd_src = (const int*)d_in[13];
    const int* dd_dst = (const int*)d_in[14];
    const int* dp_src = (const int*)d_in[15];
    const int* dp_dst = (const int*)d_in[16];
    const int* pd_src = (const int*)d_in[17];
    const int* pd_dst = (const int*)d_in[18];
    float* out = (float*)d_out;

    float *Hdd, *Hdp, *Hpd, *Adrug, *Aprot;
    float *WtDD, *WtDP, *WtPD, *WtDR, *WtPR;
    int *off_dd, *off_pd, *off_dp, *esrc_dd, *esrc_pd, *esrc_dp;
    cudaGetSymbolAddress((void**)&Hdd, g_Hdd);
    cudaGetSymbolAddress((void**)&Hdp, g_Hdp);
    cudaGetSymbolAddress((void**)&Hpd, g_Hpd);
    cudaGetSymbolAddress((void**)&Adrug, g_Adrug);
    cudaGetSymbolAddress((void**)&Aprot, g_Aprot);
    cudaGetSymbolAddress((void**)&WtDD, g_WtDD);
    cudaGetSymbolAddress((void**)&WtDP, g_WtDP);
    cudaGetSymbolAddress((void**)&WtPD, g_WtPD);
    cudaGetSymbolAddress((void**)&WtDR, g_WtDR);
    cudaGetSymbolAddress((void**)&WtPR, g_WtPR);
    cudaGetSymbolAddress((void**)&off_dd, g_off_dd);
    cudaGetSymbolAddress((void**)&off_pd, g_off_pd);
    cudaGetSymbolAddress((void**)&off_dp, g_off_dp);
    cudaGetSymbolAddress((void**)&esrc_dd, g_esrc_dd);
    cudaGetSymbolAddress((void**)&esrc_pd, g_esrc_pd);
    cudaGetSymbolAddress((void**)&esrc_dp, g_esrc_dp);

    cudaStream_t s1 = g_res.s1;
    cudaStream_t s2 = g_res.s2;

    // ---- fork s1 off the main stream ----
    cudaEventRecord(g_res.eFork, 0);
    cudaStreamWaitEvent(s1, g_res.eFork, 0);

    // ---- s1: CSR build chain ----
    zero_counts<<<256, 256, 0, s1>>>();
    count_all<<<(EDD + EPD + EDP + 255) / 256, 256, 0, s1>>>(dd_dst, pd_dst, dp_dst);
    chunk_sums<<<NCH_TOT, 1024, 0, s1>>>();
    scan_partials<<<1, 64, 0, s1>>>();
    chunk_scan<<<NCH_TOT, 1024, 0, s1>>>();
    fill_all<<<(EDD + EPD + EDP + 255) / 256, 256, 0, s1>>>(dd_src, dd_dst, pd_src, pd_dst, dp_src, dp_dst);
    cudaEventRecord(g_res.eFill, s1);

    // ---- s0: weight prep + drug/prot aggs ----
    prep_weights<<<256, 256>>>(Wagg_dd, Wagg_dp, Wagg_pd, W_drug, W_prot);
    cudaEventRecord(g_res.ePrep, 0);
    agg_gemm_relu<<<(NDRUG + 63) / 64, 256>>>(x_drug, WtDD, Hdd, NDRUG);
    cudaEventRecord(g_res.eDD, 0);
    agg_gemm_relu<<<(NPROT + 63) / 64, 256>>>(x_prot, WtPD, Hpd, NPROT);
    cudaEventRecord(g_res.ePD, 0);

    // ---- s2: drug->prot branch ----
    cudaStreamWaitEvent(s2, g_res.ePrep, 0);
    agg_gemm_relu<<<(NDRUG + 63) / 64, 256, 0, s2>>>(x_drug, WtDP, Hdp, NDRUG);
    cudaStreamWaitEvent(s2, g_res.eFill, 0);
    gather_prot<<<(NPROT * 32 + 255) / 256, 256, 0, s2>>>(Hdp, esrc_dp, off_dp, Aprot, NPROT);
    node_update<<<(NPROT + 63) / 64, 256, 0, s2>>>(
        x_prot, Aprot, WtPR, b_prot, g_prot, be_prot,
        out + (size_t)NDRUG * DD, 0, NPROT);
    cudaEventRecord(g_res.eEnd2, s2);

    // ---- s1: chunked fused drug gather (needs Hdd+Hpd via ePD + CSR on s1) ----
    cudaStreamWaitEvent(s1, g_res.ePD, 0);
    gather_drug<<<(DRUG_HALF * 32 + 255) / 256, 256, 0, s1>>>(
        Hdd, Hpd, esrc_dd, off_dd, esrc_pd, off_pd, Adrug, 0, DRUG_HALF);
    cudaEventRecord(g_res.eG0, s1);
    gather_drug<<<((NDRUG - DRUG_HALF) * 32 + 255) / 256, 256, 0, s1>>>(
        Hdd, Hpd, esrc_dd, off_dd, esrc_pd, off_pd, Adrug, DRUG_HALF, NDRUG);
    cudaEventRecord(g_res.eG1, s1);

    // ---- s0: chunked drug node update (c0 overlaps gather c1), then join ----
    cudaStreamWaitEvent(0, g_res.eG0, 0);
    node_update<<<DRUG_HALF / 64, 256>>>(
        x_drug, Adrug, WtDR, b_drug, g_drug, be_drug, out, 0, DRUG_HALF);
    cudaStreamWaitEvent(0, g_res.eG1, 0);
    node_update<<<(NDRUG - DRUG_HALF + 63) / 64, 256>>>(
        x_drug, Adrug, WtDR, b_drug, g_drug, be_drug, out, DRUG_HALF, NDRUG);
    cudaStreamWaitEvent(0, g_res.eEnd2, 0);
}

// round 15
// speedup vs baseline: 1.0068x; 1.0068x over previous
#include <cuda_runtime.h>
#include <cstdint>

#define NDRUG 100000
#define NPROT 50000
#define EDD 800000
#define EDP 600000
#define EPD 600000
#define DD 128
#define XTS 68

// chunked scan geometry
#define CH 4096
#define NCH_DD 25
#define NCH_PD 25
#define NCH_DP 13
#define NCH_TOT (NCH_DD + NCH_PD + NCH_DP)   // 63

typedef unsigned long long u64;

__device__ __forceinline__ u64 pk2(float lo, float hi) {
    u64 r; asm("mov.b64 %0,{%1,%2};" : "=l"(r) : "f"(lo), "f"(hi)); return r;
}
__device__ __forceinline__ u64 dp2(float v) {
    u64 r; asm("mov.b64 %0,{%1,%1};" : "=l"(r) : "f"(v)); return r;
}
__device__ __forceinline__ void fma2(u64& d, u64 a, u64 b) {
    asm("fma.rn.f32x2 %0,%1,%2,%3;" : "=l"(d) : "l"(a), "l"(b), "l"(d));
}
__device__ __forceinline__ void up2(u64 v, float& lo, float& hi) {
    asm("mov.b64 {%0,%1},%2;" : "=f"(lo), "=f"(hi) : "l"(v));
}

// ---------------- scratch ----------------
__device__ __align__(16) float g_Hdd[(size_t)NDRUG * DD];
__device__ __align__(16) float g_Hdp[(size_t)NDRUG * DD];
__device__ __align__(16) float g_Hpd[(size_t)NPROT * DD];
__device__ __align__(16) float g_Adrug[(size_t)NDRUG * DD];
__device__ __align__(16) float g_Aprot[(size_t)NPROT * DD];
// CSR
__device__ __align__(16) int g_cnt_dd[NDRUG];
__device__ __align__(16) int g_cnt_pd[NDRUG];
__device__ __align__(16) int g_cnt_dp[NPROT];
__device__ __align__(16) int g_off_dd[NDRUG + 4];
__device__ __align__(16) int g_off_pd[NDRUG + 4];
__device__ __align__(16) int g_off_dp[NPROT + 4];
__device__ __align__(16) int g_cur_dd[NDRUG + 4];
__device__ __align__(16) int g_cur_pd[NDRUG + 4];
__device__ __align__(16) int g_cur_dp[NPROT + 4];
__device__ int g_esrc_dd[EDD];
__device__ int g_esrc_pd[EPD];
__device__ int g_esrc_dp[EDP];
__device__ int g_part[NCH_TOT];
__device__ int g_pbase[NCH_TOT];
// transposed weights
__device__ __align__(16) float g_WtDD[DD * DD];
__device__ __align__(16) float g_WtDP[DD * DD];
__device__ __align__(16) float g_WtPD[DD * DD];
__device__ __align__(16) float g_WtDR[DD * 2 * DD];
__device__ __align__(16) float g_WtPR[DD * 2 * DD];

// ---------------- host-side stream/event resources ----------------
struct GpuRes {
    cudaStream_t s1, s2;
    cudaEvent_t eFork, ePrep, eDD, ePD, eFill, eGD, eEnd2;
    GpuRes() {
        cudaStreamCreateWithFlags(&s1, cudaStreamNonBlocking);
        cudaStreamCreateWithFlags(&s2, cudaStreamNonBlocking);
        cudaEventCreateWithFlags(&eFork, cudaEventDisableTiming);
        cudaEventCreateWithFlags(&ePrep, cudaEventDisableTiming);
        cudaEventCreateWithFlags(&eDD,   cudaEventDisableTiming);
        cudaEventCreateWithFlags(&ePD,   cudaEventDisableTiming);
        cudaEventCreateWithFlags(&eFill, cudaEventDisableTiming);
        cudaEventCreateWithFlags(&eGD,   cudaEventDisableTiming);
        cudaEventCreateWithFlags(&eEnd2, cudaEventDisableTiming);
    }
};
static GpuRes g_res;

// ---------------- weight transpose ----------------
__global__ void prep_weights(const float* __restrict__ Wdd, const float* __restrict__ Wdp,
                             const float* __restrict__ Wpd, const float* __restrict__ Wdr,
                             const float* __restrict__ Wpr)
{
    int t = blockIdx.x * blockDim.x + threadIdx.x;
    int stride = gridDim.x * blockDim.x;
    for (int i = t; i < DD * DD; i += stride) {
        int c = i >> 7, k = i & 127;
        g_WtDD[k * DD + c] = Wdd[i];
        g_WtDP[k * DD + c] = Wdp[i];
        g_WtPD[k * DD + c] = Wpd[i];
    }
    for (int i = t; i < DD * 2 * DD; i += stride) {
        int c = i >> 8, col = i & 255;
        int k = col & 127, half = col >> 7;
        g_WtDR[k * 256 + half * 128 + c] = Wdr[i];
        g_WtPR[k * 256 + half * 128 + c] = Wpr[i];
    }
}

// ---------------- CSR build ----------------
__global__ void zero_counts() {
    int t = blockIdx.x * blockDim.x + threadIdx.x;
    int stride = gridDim.x * blockDim.x;
    for (int i = t; i < NDRUG; i += stride) { g_cnt_dd[i] = 0; g_cnt_pd[i] = 0; }
    for (int i = t; i < NPROT; i += stride) g_cnt_dp[i] = 0;
}

__global__ void count_all(const int* __restrict__ dd, const int* __restrict__ pd,
                          const int* __restrict__ dp) {
    int t = blockIdx.x * blockDim.x + threadIdx.x;
    if (t < EDD) atomicAdd(&g_cnt_dd[__ldg(&dd[t])], 1);
    else if (t < EDD + EPD) atomicAdd(&g_cnt_pd[__ldg(&pd[t - EDD])], 1);
    else if (t < EDD + EPD + EDP) atomicAdd(&g_cnt_dp[__ldg(&dp[t - EDD - EPD])], 1);
}

__device__ __forceinline__ void chunk_map(int b, const int*& cnt, int*& offs, int*& cur,
                                          int& base, int& n) {
    if (b < NCH_DD)              { cnt = g_cnt_dd; offs = g_off_dd; cur = g_cur_dd; base = b * CH; n = NDRUG; }
    else if (b < NCH_DD + NCH_PD){ cnt = g_cnt_pd; offs = g_off_pd; cur = g_cur_pd; base = (b - NCH_DD) * CH; n = NDRUG; }
    else                         { cnt = g_cnt_dp; offs = g_off_dp; cur = g_cur_dp; base = (b - NCH_DD - NCH_PD) * CH; n = NPROT; }
}

__global__ __launch_bounds__(1024) void chunk_sums() {
    const int* cnt; int* offs; int* cur; int base, n;
    chunk_map(blockIdx.x, cnt, offs, cur, base, n);
    int i0 = base + threadIdx.x * 4;
    int4 c = make_int4(0, 0, 0, 0);
    if (i0 < n) c = *reinterpret_cast<const int4*>(&cnt[i0]);
    int tot = c.x + c.y + c.z + c.w;
    __shared__ int ws[32];
    int lane = threadIdx.x & 31, wid = threadIdx.x >> 5;
#pragma unroll
    for (int o = 16; o; o >>= 1) tot += __shfl_xor_sync(0xFFFFFFFFu, tot, o);
    if (lane == 0) ws[wid] = tot;
    __syncthreads();
    if (wid == 0) {
        int v = ws[lane];
#pragma unroll
        for (int o = 16; o; o >>= 1) v += __shfl_xor_sync(0xFFFFFFFFu, v, o);
        if (lane == 0) g_part[blockIdx.x] = v;
    }
}

__global__ void scan_partials() {
    __shared__ int s[64];
    int t = threadIdx.x;
    int v = (t < NCH_TOT) ? g_part[t] : 0;
    s[t] = v;
    __syncthreads();
#pragma unroll
    for (int o = 1; o < 64; o <<= 1) {
        int add = (t >= o) ? s[t - o] : 0;
        __syncthreads();
        s[t] += add;
        __syncthreads();
    }
    if (t < NCH_TOT) {
        int excl = s[t] - v;
        int segoff = (t >= NCH_DD + NCH_PD) ? (EDD + EPD) : (t >= NCH_DD ? EDD : 0);
        g_pbase[t] = excl - segoff;
    }
    if (t == 0) {
        g_off_dd[NDRUG] = EDD;
        g_off_pd[NDRUG] = EPD;
        g_off_dp[NPROT] = EDP;
    }
}

__global__ __launch_bounds__(1024) void chunk_scan() {
    const int* cnt; int* offs; int* cur; int base, n;
    chunk_map(blockIdx.x, cnt, offs, cur, base, n);
    int carry = g_pbase[blockIdx.x];
    __shared__ int wsum[32];
    int tid = threadIdx.x, lane = tid & 31, wid = tid >> 5;
    int i0 = base + tid * 4;
    int4 c = make_int4(0, 0, 0, 0);
    if (i0 < n) c = *reinterpret_cast<const int4*>(&cnt[i0]);
    int tot = c.x + c.y + c.z + c.w;
    int incl = tot;
#pragma unroll
    for (int o = 1; o < 32; o <<= 1) {
        int v = __shfl_up_sync(0xFFFFFFFFu, incl, o);
        if (lane >= o) incl += v;
    }
    if (lane == 31) wsum[wid] = incl;
    __syncthreads();
    if (wid == 0) {
        int v = wsum[lane];
        int wincl = v;
#pragma unroll
        for (int o = 1; o < 32; o <<= 1) {
            int t2 = __shfl_up_sync(0xFFFFFFFFu, wincl, o);
            if (lane >= o) wincl += t2;
        }
        wsum[lane] = wincl - v;
    }
    __syncthreads();
    int excl = carry + wsum[wid] + incl - tot;
    if (i0 < n) {
        int e0 = excl, e1 = e0 + c.x, e2 = e1 + c.y, e3 = e2 + c.z;
        *reinterpret_cast<int4*>(&offs[i0]) = make_int4(e0, e1, e2, e3);
        *reinterpret_cast<int4*>(&cur[i0])  = make_int4(e0, e1, e2, e3);
    }
}

__global__ void fill_all(const int* __restrict__ dd_s, const int* __restrict__ dd_d,
                         const int* __restrict__ pd_s, const int* __restrict__ pd_d,
                         const int* __restrict__ dp_s, const int* __restrict__ dp_d) {
    int t = blockIdx.x * blockDim.x + threadIdx.x;
    if (t < EDD) {
        int slot = atomicAdd(&g_cur_dd[__ldg(&dd_d[t])], 1);
        g_esrc_dd[slot] = __ldg(&dd_s[t]);
    } else if (t < EDD + EPD) {
        int e = t - EDD;
        int slot = atomicAdd(&g_cur_pd[__ldg(&pd_d[e])], 1);
        g_esrc_pd[slot] = __ldg(&pd_s[e]);
    } else if (t < EDD + EPD + EDP) {
        int e = t - EDD - EPD;
        int slot = atomicAdd(&g_cur_dp[__ldg(&dp_d[e])], 1);
        g_esrc_dp[slot] = __ldg(&dp_s[e]);
    }
}

// ---------------- GEMM + ReLU (proven version) ----------------
__global__ __launch_bounds__(256, 3) void agg_gemm_relu(
    const float* __restrict__ X, const float* __restrict__ Wt,
    float* __restrict__ H, int N)
{
    __shared__ float xt[DD * XTS];

    int tid = threadIdx.x;
    int row0 = blockIdx.x * 64;
    for (int j = tid; j < 64 * 32; j += 256) {
        int r = j & 63, qg = j >> 6;
        int row = row0 + r;
        float4 v = make_float4(0.f, 0.f, 0.f, 0.f);
        if (row < N) v = *reinterpret_cast<const float4*>(&X[(size_t)row * DD + qg * 4]);
        xt[(qg * 4 + 0) * XTS + r] = v.x;
        xt[(qg * 4 + 1) * XTS + r] = v.y;
        xt[(qg * 4 + 2) * XTS + r] = v.z;
        xt[(qg * 4 + 3) * XTS + r] = v.w;
    }
    __syncthreads();

    int ct = tid & 31, rt = tid >> 5;
    int c0 = ct * 4, r0 = rt * 8;
    u64 acc[4][4];
#pragma unroll
    for (int rp = 0; rp < 4; rp++)
#pragma unroll
        for (int c = 0; c < 4; c++) acc[rp][c] = 0ull;

#pragma unroll 4
    for (int k = 0; k < DD; k++) {
        float4 w = __ldg(reinterpret_cast<const float4*>(&Wt[k * DD + c0]));
        float4 xa = *reinterpret_cast<const float4*>(&xt[k * XTS + r0]);
        float4 xb = *reinterpret_cast<const float4*>(&xt[k * XTS + r0 + 4]);
        u64 xp[4] = {pk2(xa.x, xa.y), pk2(xa.z, xa.w), pk2(xb.x, xb.y), pk2(xb.z, xb.w)};
        u64 wd[4] = {dp2(w.x), dp2(w.y), dp2(w.z), dp2(w.w)};
#pragma unroll
        for (int rp = 0; rp < 4; rp++)
#pragma unroll
            for (int c = 0; c < 4; c++) fma2(acc[rp][c], xp[rp], wd[c]);
    }

#pragma unroll
    for (int rp = 0; rp < 4; rp++) {
        float lo[4], hi[4];
#pragma unroll
        for (int c = 0; c < 4; c++) up2(acc[rp][c], lo[c], hi[c]);
        int ra = row0 + r0 + 2 * rp;
        if (ra < N) {
            float4 o = make_float4(fmaxf(lo[0], 0.f), fmaxf(lo[1], 0.f),
                                   fmaxf(lo[2], 0.f), fmaxf(lo[3], 0.f));
            *reinterpret_cast<float4*>(&H[(size_t)ra * DD + c0]) = o;
        }
        if (ra + 1 < N) {
            float4 o = make_float4(fmaxf(hi[0], 0.f), fmaxf(hi[1], 0.f),
                                   fmaxf(hi[2], 0.f), fmaxf(hi[3], 0.f));
            *reinterpret_cast<float4*>(&H[(size_t)(ra + 1) * DD + c0]) = o;
        }
    }
}

// ---------------- 8-deep accumulate helper ----------------
__device__ __forceinline__ void acc_edges8(
    const float* __restrict__ H, const int* __restrict__ esrc,
    int e, int lane, float4& acc)
{
    int s[8];
#pragma unroll
    for (int i = 0; i < 8; i++) s[i] = __ldg(&esrc[e + i]);
    float4 v[8];
#pragma unroll
    for (int i = 0; i < 8; i++)
        v[i] = __ldg(reinterpret_cast<const float4*>(&H[(size_t)s[i] * DD + lane * 4]));
#pragma unroll
    for (int i = 0; i < 8; i++) {
        acc.x += v[i].x; acc.y += v[i].y; acc.z += v[i].z; acc.w += v[i].w;
    }
}

// ---------------- fused drug gather: A = 0.5*(mean_dd(Hdd) + mean_pd(Hpd)) ----------------
__global__ __launch_bounds__(256) void gather_drug(
    const float* __restrict__ Hdd, const float* __restrict__ Hpd,
    const int* __restrict__ esrc_dd, const int* __restrict__ off_dd,
    const int* __restrict__ esrc_pd, const int* __restrict__ off_pd,
    float* __restrict__ A, int N)
{
    int w = (blockIdx.x * blockDim.x + threadIdx.x) >> 5;
    if (w >= N) return;
    int lane = threadIdx.x & 31;
    float4 o = make_float4(0.f, 0.f, 0.f, 0.f);
#pragma unroll
    for (int rel = 0; rel < 2; rel++) {
        const float* H = rel ? Hpd : Hdd;
        const int* esrc = rel ? esrc_pd : esrc_dd;
        const int* offs = rel ? off_pd : off_dd;
        int beg = __ldg(&offs[w]), end = __ldg(&offs[w + 1]);
        float4 acc = make_float4(0.f, 0.f, 0.f, 0.f);
        int e = beg;
        for (; e + 8 <= end; e += 8) acc_edges8(H, esrc, e, lane, acc);
        for (; e + 4 <= end; e += 4) {
            int s0 = __ldg(&esrc[e]);
            int s1 = __ldg(&esrc[e + 1]);
            int s2 = __ldg(&esrc[e + 2]);
            int s3 = __ldg(&esrc[e + 3]);
            float4 v0 = __ldg(reinterpret_cast<const float4*>(&H[(size_t)s0 * DD + lane * 4]));
            float4 v1 = __ldg(reinterpret_cast<const float4*>(&H[(size_t)s1 * DD + lane * 4]));
            float4 v2 = __ldg(reinterpret_cast<const float4*>(&H[(size_t)s2 * DD + lane * 4]));
            float4 v3 = __ldg(reinterpret_cast<const float4*>(&H[(size_t)s3 * DD + lane * 4]));
            acc.x += (v0.x + v1.x) + (v2.x + v3.x);
            acc.y += (v0.y + v1.y) + (v2.y + v3.y);
            acc.z += (v0.z + v1.z) + (v2.z + v3.z);
            acc.w += (v0.w + v1.w) + (v2.w + v3.w);
        }
        for (; e < end; e++) {
            int s = __ldg(&esrc[e]);
            float4 v = __ldg(reinterpret_cast<const float4*>(&H[(size_t)s * DD + lane * 4]));
            acc.x += v.x; acc.y += v.y; acc.z += v.z; acc.w += v.w;
        }
        float inv = 0.5f / fmaxf((float)(end - beg), 1.0f);
        o.x += acc.x * inv; o.y += acc.y * inv; o.z += acc.z * inv; o.w += acc.w * inv;
    }
    *reinterpret_cast<float4*>(&A[(size_t)w * DD + lane * 4]) = o;
}

// ---------------- prot gather (single relation, direct mean) ----------------
__global__ __launch_bounds__(256) void gather_prot(
    const float* __restrict__ H, const int* __restrict__ esrc,
    const int* __restrict__ offs, float* __restrict__ A, int N)
{
    int w = (blockIdx.x * blockDim.x + threadIdx.x) >> 5;
    if (w >= N) return;
    int lane = threadIdx.x & 31;
    int beg = __ldg(&offs[w]), end = __ldg(&offs[w + 1]);
    float4 acc = make_float4(0.f, 0.f, 0.f, 0.f);
    int e = beg;
    for (; e + 8 <= end; e += 8) acc_edges8(H, esrc, e, lane, acc);
    for (; e + 4 <= end; e += 4) {
        int s0 = __ldg(&esrc[e]);
        int s1 = __ldg(&esrc[e + 1]);
        int s2 = __ldg(&esrc[e + 2]);
        int s3 = __ldg(&esrc[e + 3]);
        float4 v0 = __ldg(reinterpret_cast<const float4*>(&H[(size_t)s0 * DD + lane * 4]));
        float4 v1 = __ldg(reinterpret_cast<const float4*>(&H[(size_t)s1 * DD + lane * 4]));
        float4 v2 = __ldg(reinterpret_cast<const float4*>(&H[(size_t)s2 * DD + lane * 4]));
        float4 v3 = __ldg(reinterpret_cast<const float4*>(&H[(size_t)s3 * DD + lane * 4]));
        acc.x += (v0.x + v1.x) + (v2.x + v3.x);
        acc.y += (v0.y + v1.y) + (v2.y + v3.y);
        acc.z += (v0.z + v1.z) + (v2.z + v3.z);
        acc.w += (v0.w + v1.w) + (v2.w + v3.w);
    }
    for (; e < end; e++) {
        int s = __ldg(&esrc[e]);
        float4 v = __ldg(reinterpret_cast<const float4*>(&H[(size_t)s * DD + lane * 4]));
        acc.x += v.x; acc.y += v.y; acc.z += v.z; acc.w += v.w;
    }
    float inv = 1.0f / fmaxf((float)(end - beg), 1.0f);
    *reinterpret_cast<float4*>(&A[(size_t)w * DD + lane * 4]) =
        make_float4(acc.x * inv, acc.y * inv, acc.z * inv, acc.w * inv);
}

// ---------------- fused node update (proven version) ----------------
__global__ __launch_bounds__(256, 2) void node_update(
    const float* __restrict__ X,
    const float* __restrict__ A,
    const float* __restrict__ Wt,
    const float* __restrict__ b,
    const float* __restrict__ g,
    const float* __restrict__ be,
    float* __restrict__ out, int N)
{
    __shared__ float xt[DD * XTS];
    __shared__ float at[DD * XTS];

    int tid = threadIdx.x;
    int row0 = blockIdx.x * 64;
    for (int j = tid; j < 64 * 32; j += 256) {
        int r = j & 63, qg = j >> 6;
        int row = row0 + r;
        float4 xv = make_float4(0.f, 0.f, 0.f, 0.f);
        float4 av = make_float4(0.f, 0.f, 0.f, 0.f);
        if (row < N) {
            xv = *reinterpret_cast<const float4*>(&X[(size_t)row * DD + qg * 4]);
            av = *reinterpret_cast<const float4*>(&A[(size_t)row * DD + qg * 4]);
        }
        xt[(qg * 4 + 0) * XTS + r] = xv.x;
        xt[(qg * 4 + 1) * XTS + r] = xv.y;
        xt[(qg * 4 + 2) * XTS + r] = xv.z;
        xt[(qg * 4 + 3) * XTS + r] = xv.w;
        at[(qg * 4 + 0) * XTS + r] = av.x;
        at[(qg * 4 + 1) * XTS + r] = av.y;
        at[(qg * 4 + 2) * XTS + r] = av.z;
        at[(qg * 4 + 3) * XTS + r] = av.w;
    }
    __syncthreads();

    int ct = tid & 31, rt = tid >> 5;
    int c0 = ct * 4, r0 = rt * 8;
    u64 acc[4][4];
#pragma unroll
    for (int rp = 0; rp < 4; rp++)
#pragma unroll
        for (int c = 0; c < 4; c++) acc[rp][c] = 0ull;

#pragma unroll 2
    for (int k = 0; k < DD; k++) {
        float4 w1 = __ldg(reinterpret_cast<const float4*>(&Wt[k * 256 + c0]));
        float4 w2 = __ldg(reinterpret_cast<const float4*>(&Wt[k * 256 + 128 + c0]));
        float4 xa = *reinterpret_cast<const float4*>(&xt[k * XTS + r0]);
        float4 xb = *reinterpret_cast<const float4*>(&xt[k * XTS + r0 + 4]);
        float4 aa = *reinterpret_cast<const float4*>(&at[k * XTS + r0]);
        float4 ab = *reinterpret_cast<const float4*>(&at[k * XTS + r0 + 4]);
        u64 xp[4] = {pk2(xa.x, xa.y), pk2(xa.z, xa.w), pk2(xb.x, xb.y), pk2(xb.z, xb.w)};
        u64 ap[4] = {pk2(aa.x, aa.y), pk2(aa.z, aa.w), pk2(ab.x, ab.y), pk2(ab.z, ab.w)};
        u64 w1d[4] = {dp2(w1.x), dp2(w1.y), dp2(w1.z), dp2(w1.w)};
        u64 w2d[4] = {dp2(w2.x), dp2(w2.y), dp2(w2.z), dp2(w2.w)};
#pragma unroll
        for (int rp = 0; rp < 4; rp++)
#pragma unroll
            for (int c = 0; c < 4; c++) {
                fma2(acc[rp][c], xp[rp], w1d[c]);
                fma2(acc[rp][c], ap[rp], w2d[c]);
            }
    }
    float4 bb = *reinterpret_cast<const float4*>(&b[c0]);
    __syncthreads();
    float* hs = xt;

#pragma unroll
    for (int rp = 0; rp < 4; rp++) {
        float lo[4], hi[4];
#pragma unroll
        for (int c = 0; c < 4; c++) up2(acc[rp][c], lo[c], hi[c]);
        int rla = r0 + 2 * rp;
        int ra = row0 + rla;
        float4 xra = make_float4(0.f, 0.f, 0.f, 0.f);
        float4 xrb = make_float4(0.f, 0.f, 0.f, 0.f);
        if (ra < N)     xra = *reinterpret_cast<const float4*>(&X[(size_t)ra * DD + c0]);
        if (ra + 1 < N) xrb = *reinterpret_cast<const float4*>(&X[(size_t)(ra + 1) * DD + c0]);
        float4 oa, ob;
        oa.x = fmaxf(lo[0] + bb.x, 0.f) + xra.x;
        oa.y = fmaxf(lo[1] + bb.y, 0.f) + xra.y;
        oa.z = fmaxf(lo[2] + bb.z, 0.f) + xra.z;
        oa.w = fmaxf(lo[3] + bb.w, 0.f) + xra.w;
        ob.x = fmaxf(hi[0] + bb.x, 0.f) + xrb.x;
        ob.y = fmaxf(hi[1] + bb.y, 0.f) + xrb.y;
        ob.z = fmaxf(hi[2] + bb.z, 0.f) + xrb.z;
        ob.w = fmaxf(hi[3] + bb.w, 0.f) + xrb.w;
        *reinterpret_cast<float4*>(&hs[rla * DD + c0]) = oa;
        *reinterpret_cast<float4*>(&hs[(rla + 1) * DD + c0]) = ob;
    }
    __syncthreads();

    int lane = tid & 31;
    float4 gg  = *reinterpret_cast<const float4*>(&g[lane * 4]);
    float4 bev = *reinterpret_cast<const float4*>(&be[lane * 4]);
    for (int r = 0; r < 8; r++) {
        int rl = rt * 8 + r;
        int row = row0 + rl;
        float4 v = *reinterpret_cast<const float4*>(&hs[rl * DD + lane * 4]);
        float s  = v.x + v.y + v.z + v.w;
        float s2 = v.x * v.x + v.y * v.y + v.z * v.z + v.w * v.w;
#pragma unroll
        for (int o_ = 16; o_; o_ >>= 1) {
            s  += __shfl_xor_sync(0xFFFFFFFFu, s, o_);
            s2 += __shfl_xor_sync(0xFFFFFFFFu, s2, o_);
        }
        float mu  = s * (1.0f / 128.0f);
        float var = s2 * (1.0f / 128.0f) - mu * mu;
        float rstd = rsqrtf(var + 1e-5f);
        if (row < N) {
            float4 o;
            o.x = (v.x - mu) * rstd * gg.x + bev.x;
            o.y = (v.y - mu) * rstd * gg.y + bev.y;
            o.z = (v.z - mu) * rstd * gg.z + bev.z;
            o.w = (v.w - mu) * rstd * gg.w + bev.w;
            *reinterpret_cast<float4*>(&out[(size_t)row * DD + lane * 4]) = o;
        }
    }
}

// ---------------- launch: R12 three-branch DAG (proven 551.7us schedule) ----------------
extern "C" void kernel_launch(void* const* d_in, const int* in_sizes, int n_in,
                              void* d_out, int out_size)
{
    const float* x_drug  = (const float*)d_in[0];
    const float* x_prot  = (const float*)d_in[1];
    const float* Wagg_dd = (const float*)d_in[2];
    const float* Wagg_dp = (const float*)d_in[3];
    const float* Wagg_pd = (const float*)d_in[4];
    const float* W_drug  = (const float*)d_in[5];
    const float* b_drug  = (const float*)d_in[6];
    const float* W_prot  = (const float*)d_in[7];
    const float* b_prot  = (const float*)d_in[8];
    const float* g_drug  = (const float*)d_in[9];
    const float* be_drug = (const float*)d_in[10];
    const float* g_prot  = (const float*)d_in[11];
    const float* be_prot = (const float*)d_in[12];
    const int* dd_src = (const int*)d_in[13];
    const int* dd_dst = (const int*)d_in[14];
    const int* dp_src = (const int*)d_in[15];
    const int* dp_dst = (const int*)d_in[16];
    const int* pd_src = (const int*)d_in[17];
    const int* pd_dst = (const int*)d_in[18];
    float* out = (float*)d_out;

    float *Hdd, *Hdp, *Hpd, *Adrug, *Aprot;
    float *WtDD, *WtDP, *WtPD, *WtDR, *WtPR;
    int *off_dd, *off_pd, *off_dp, *esrc_dd, *esrc_pd, *esrc_dp;
    cudaGetSymbolAddress((void**)&Hdd, g_Hdd);
    cudaGetSymbolAddress((void**)&Hdp, g_Hdp);
    cudaGetSymbolAddress((void**)&Hpd, g_Hpd);
    cudaGetSymbolAddress((void**)&Adrug, g_Adrug);
    cudaGetSymbolAddress((void**)&Aprot, g_Aprot);
    cudaGetSymbolAddress((void**)&WtDD, g_WtDD);
    cudaGetSymbolAddress((void**)&WtDP, g_WtDP);
    cudaGetSymbolAddress((void**)&WtPD, g_WtPD);
    cudaGetSymbolAddress((void**)&WtDR, g_WtDR);
    cudaGetSymbolAddress((void**)&WtPR, g_WtPR);
    cudaGetSymbolAddress((void**)&off_dd, g_off_dd);
    cudaGetSymbolAddress((void**)&off_pd, g_off_pd);
    cudaGetSymbolAddress((void**)&off_dp, g_off_dp);
    cudaGetSymbolAddress((void**)&esrc_dd, g_esrc_dd);
    cudaGetSymbolAddress((void**)&esrc_pd, g_esrc_pd);
    cudaGetSymbolAddress((void**)&esrc_dp, g_esrc_dp);

    cudaStream_t s1 = g_res.s1;
    cudaStream_t s2 = g_res.s2;

    // ---- fork s1 off the main stream ----
    cudaEventRecord(g_res.eFork, 0);
    cudaStreamWaitEvent(s1, g_res.eFork, 0);

    // ---- s1: CSR build chain ----
    zero_counts<<<256, 256, 0, s1>>>();
    count_all<<<(EDD + EPD + EDP + 255) / 256, 256, 0, s1>>>(dd_dst, pd_dst, dp_dst);
    chunk_sums<<<NCH_TOT, 1024, 0, s1>>>();
    scan_partials<<<1, 64, 0, s1>>>();
    chunk_scan<<<NCH_TOT, 1024, 0, s1>>>();
    fill_all<<<(EDD + EPD + EDP + 255) / 256, 256, 0, s1>>>(dd_src, dd_dst, pd_src, pd_dst, dp_src, dp_dst);
    cudaEventRecord(g_res.eFill, s1);

    // ---- s0: weight prep + drug/prot aggs ----
    prep_weights<<<256, 256>>>(Wagg_dd, Wagg_dp, Wagg_pd, W_drug, W_prot);
    cudaEventRecord(g_res.ePrep, 0);
    agg_gemm_relu<<<(NDRUG + 63) / 64, 256>>>(x_drug, WtDD, Hdd, NDRUG);
    cudaEventRecord(g_res.eDD, 0);
    agg_gemm_relu<<<(NPROT + 63) / 64, 256>>>(x_prot, WtPD, Hpd, NPROT);
    cudaEventRecord(g_res.ePD, 0);

    // ---- s2: drug->prot branch (independent of node_drug) ----
    cudaStreamWaitEvent(s2, g_res.ePrep, 0);
    agg_gemm_relu<<<(NDRUG + 63) / 64, 256, 0, s2>>>(x_drug, WtDP, Hdp, NDRUG);
    cudaStreamWaitEvent(s2, g_res.eFill, 0);
    gather_prot<<<(NPROT * 32 + 255) / 256, 256, 0, s2>>>(Hdp, esrc_dp, off_dp, Aprot, NPROT);
    node_update<<<(NPROT + 63) / 64, 256, 0, s2>>>(
        x_prot, Aprot, WtPR, b_prot, g_prot, be_prot,
        out + (size_t)NDRUG * DD, NPROT);
    cudaEventRecord(g_res.eEnd2, s2);

    // ---- s1: fused drug gather (needs Hdd + Hpd; ePD covers both, + CSR on s1) ----
    cudaStreamWaitEvent(s1, g_res.ePD, 0);
    gather_drug<<<(NDRUG * 32 + 255) / 256, 256, 0, s1>>>(
        Hdd, Hpd, esrc_dd, off_dd, esrc_pd, off_pd, Adrug, NDRUG);
    cudaEventRecord(g_res.eGD, s1);

    // ---- s0: drug node update, then join ----
    cudaStreamWaitEvent(0, g_res.eGD, 0);
    node_update<<<(NDRUG + 63) / 64, 256>>>(
        x_drug, Adrug, WtDR, b_drug, g_drug, be_drug, out, NDRUG);
    cudaStreamWaitEvent(0, g_res.eEnd2, 0);
}

// round 16
// speedup vs baseline: 1.0240x; 1.0172x over previous
#include <cuda_runtime.h>
#include <cstdint>

#define NDRUG 100000
#define NPROT 50000
#define EDD 800000
#define EDP 600000
#define EPD 600000
#define DD 128
#define XTS 68

// chunked scan geometry
#define CH 4096
#define NCH_DD 25
#define NCH_PD 25
#define NCH_DP 13
#define NCH_TOT (NCH_DD + NCH_PD + NCH_DP)   // 63

typedef unsigned long long u64;

__device__ __forceinline__ u64 pk2(float lo, float hi) {
    u64 r; asm("mov.b64 %0,{%1,%2};" : "=l"(r) : "f"(lo), "f"(hi)); return r;
}
__device__ __forceinline__ u64 dp2(float v) {
    u64 r; asm("mov.b64 %0,{%1,%1};" : "=l"(r) : "f"(v)); return r;
}
__device__ __forceinline__ void fma2(u64& d, u64 a, u64 b) {
    asm("fma.rn.f32x2 %0,%1,%2,%3;" : "=l"(d) : "l"(a), "l"(b), "l"(d));
}
__device__ __forceinline__ void up2(u64 v, float& lo, float& hi) {
    asm("mov.b64 {%0,%1},%2;" : "=f"(lo), "=f"(hi) : "l"(v));
}

// ---------------- scratch ----------------
__device__ __align__(16) float g_Hdd[(size_t)NDRUG * DD];
__device__ __align__(16) float g_Hdp[(size_t)NDRUG * DD];
__device__ __align__(16) float g_Hpd[(size_t)NPROT * DD];
__device__ __align__(16) float g_Adrug[(size_t)NDRUG * DD];
__device__ __align__(16) float g_Aprot[(size_t)NPROT * DD];
// CSR
__device__ __align__(16) int g_cnt_dd[NDRUG];
__device__ __align__(16) int g_cnt_pd[NDRUG];
__device__ __align__(16) int g_cnt_dp[NPROT];
__device__ __align__(16) int g_off_dd[NDRUG + 4];
__device__ __align__(16) int g_off_pd[NDRUG + 4];
__device__ __align__(16) int g_off_dp[NPROT + 4];
__device__ __align__(16) int g_cur_dd[NDRUG + 4];
__device__ __align__(16) int g_cur_pd[NDRUG + 4];
__device__ __align__(16) int g_cur_dp[NPROT + 4];
__device__ int g_esrc_dd[EDD];
__device__ int g_esrc_pd[EPD];
__device__ int g_esrc_dp[EDP];
__device__ int g_part[NCH_TOT];
__device__ int g_pbase[NCH_TOT];
// transposed weights
__device__ __align__(16) float g_WtDD[DD * DD];
__device__ __align__(16) float g_WtDP[DD * DD];
__device__ __align__(16) float g_WtPD[DD * DD];
__device__ __align__(16) float g_WtDR[DD * 2 * DD];
__device__ __align__(16) float g_WtPR[DD * 2 * DD];

// ---------------- host-side stream/event resources ----------------
struct GpuRes {
    cudaStream_t s1, s2;
    cudaEvent_t eFork, ePrepA, ePrepN, ePD, eFill, eGD, eEnd2;
    GpuRes() {
        cudaStreamCreateWithFlags(&s1, cudaStreamNonBlocking);
        cudaStreamCreateWithFlags(&s2, cudaStreamNonBlocking);
        cudaEventCreateWithFlags(&eFork,  cudaEventDisableTiming);
        cudaEventCreateWithFlags(&ePrepA, cudaEventDisableTiming);
        cudaEventCreateWithFlags(&ePrepN, cudaEventDisableTiming);
        cudaEventCreateWithFlags(&ePD,    cudaEventDisableTiming);
        cudaEventCreateWithFlags(&eFill,  cudaEventDisableTiming);
        cudaEventCreateWithFlags(&eGD,    cudaEventDisableTiming);
        cudaEventCreateWithFlags(&eEnd2,  cudaEventDisableTiming);
    }
};
static GpuRes g_res;

// ---------------- weight transpose: agg weights only (critical path) ----------------
__global__ void prep_agg(const float* __restrict__ Wdd, const float* __restrict__ Wdp,
                         const float* __restrict__ Wpd)
{
    int t = blockIdx.x * blockDim.x + threadIdx.x;
    int stride = gridDim.x * blockDim.x;
    for (int i = t; i < DD * DD; i += stride) {
        int c = i >> 7, k = i & 127;
        g_WtDD[k * DD + c] = Wdd[i];
        g_WtDP[k * DD + c] = Wdp[i];
        g_WtPD[k * DD + c] = Wpd[i];
    }
}

// ---------------- weight transpose: node weights (off critical path, s2) ----------------
__global__ void prep_node(const float* __restrict__ Wdr, const float* __restrict__ Wpr)
{
    int t = blockIdx.x * blockDim.x + threadIdx.x;
    int stride = gridDim.x * blockDim.x;
    for (int i = t; i < DD * 2 * DD; i += stride) {
        int c = i >> 8, col = i & 255;
        int k = col & 127, half = col >> 7;
        g_WtDR[k * 256 + half * 128 + c] = Wdr[i];
        g_WtPR[k * 256 + half * 128 + c] = Wpr[i];
    }
}

// ---------------- CSR build ----------------
__global__ void zero_counts() {
    int t = blockIdx.x * blockDim.x + threadIdx.x;
    int stride = gridDim.x * blockDim.x;
    for (int i = t; i < NDRUG; i += stride) { g_cnt_dd[i] = 0; g_cnt_pd[i] = 0; }
    for (int i = t; i < NPROT; i += stride) g_cnt_dp[i] = 0;
}

__global__ void count_all(const int* __restrict__ dd, const int* __restrict__ pd,
                          const int* __restrict__ dp) {
    int t = blockIdx.x * blockDim.x + threadIdx.x;
    if (t < EDD) atomicAdd(&g_cnt_dd[__ldg(&dd[t])], 1);
    else if (t < EDD + EPD) atomicAdd(&g_cnt_pd[__ldg(&pd[t - EDD])], 1);
    else if (t < EDD + EPD + EDP) atomicAdd(&g_cnt_dp[__ldg(&dp[t - EDD - EPD])], 1);
}

__device__ __forceinline__ void chunk_map(int b, const int*& cnt, int*& offs, int*& cur,
                                          int& base, int& n) {
    if (b < NCH_DD)              { cnt = g_cnt_dd; offs = g_off_dd; cur = g_cur_dd; base = b * CH; n = NDRUG; }
    else if (b < NCH_DD + NCH_PD){ cnt = g_cnt_pd; offs = g_off_pd; cur = g_cur_pd; base = (b - NCH_DD) * CH; n = NDRUG; }
    else                         { cnt = g_cnt_dp; offs = g_off_dp; cur = g_cur_dp; base = (b - NCH_DD - NCH_PD) * CH; n = NPROT; }
}

__global__ __launch_bounds__(1024) void chunk_sums() {
    const int* cnt; int* offs; int* cur; int base, n;
    chunk_map(blockIdx.x, cnt, offs, cur, base, n);
    int i0 = base + threadIdx.x * 4;
    int4 c = make_int4(0, 0, 0, 0);
    if (i0 < n) c = *reinterpret_cast<const int4*>(&cnt[i0]);
    int tot = c.x + c.y + c.z + c.w;
    __shared__ int ws[32];
    int lane = threadIdx.x & 31, wid = threadIdx.x >> 5;
#pragma unroll
    for (int o = 16; o; o >>= 1) tot += __shfl_xor_sync(0xFFFFFFFFu, tot, o);
    if (lane == 0) ws[wid] = tot;
    __syncthreads();
    if (wid == 0) {
        int v = ws[lane];
#pragma unroll
        for (int o = 16; o; o >>= 1) v += __shfl_xor_sync(0xFFFFFFFFu, v, o);
        if (lane == 0) g_part[blockIdx.x] = v;
    }
}

__global__ void scan_partials() {
    __shared__ int s[64];
    int t = threadIdx.x;
    int v = (t < NCH_TOT) ? g_part[t] : 0;
    s[t] = v;
    __syncthreads();
#pragma unroll
    for (int o = 1; o < 64; o <<= 1) {
        int add = (t >= o) ? s[t - o] : 0;
        __syncthreads();
        s[t] += add;
        __syncthreads();
    }
    if (t < NCH_TOT) {
        int excl = s[t] - v;
        int segoff = (t >= NCH_DD + NCH_PD) ? (EDD + EPD) : (t >= NCH_DD ? EDD : 0);
        g_pbase[t] = excl - segoff;
    }
    if (t == 0) {
        g_off_dd[NDRUG] = EDD;
        g_off_pd[NDRUG] = EPD;
        g_off_dp[NPROT] = EDP;
    }
}

__global__ __launch_bounds__(1024) void chunk_scan() {
    const int* cnt; int* offs; int* cur; int base, n;
    chunk_map(blockIdx.x, cnt, offs, cur, base, n);
    int carry = g_pbase[blockIdx.x];
    __shared__ int wsum[32];
    int tid = threadIdx.x, lane = tid & 31, wid = tid >> 5;
    int i0 = base + tid * 4;
    int4 c = make_int4(0, 0, 0, 0);
    if (i0 < n) c = *reinterpret_cast<const int4*>(&cnt[i0]);
    int tot = c.x + c.y + c.z + c.w;
    int incl = tot;
#pragma unroll
    for (int o = 1; o < 32; o <<= 1) {
        int v = __shfl_up_sync(0xFFFFFFFFu, incl, o);
        if (lane >= o) incl += v;
    }
    if (lane == 31) wsum[wid] = incl;
    __syncthreads();
    if (wid == 0) {
        int v = wsum[lane];
        int wincl = v;
#pragma unroll
        for (int o = 1; o < 32; o <<= 1) {
            int t2 = __shfl_up_sync(0xFFFFFFFFu, wincl, o);
            if (lane >= o) wincl += t2;
        }
        wsum[lane] = wincl - v;
    }
    __syncthreads();
    int excl = carry + wsum[wid] + incl - tot;
    if (i0 < n) {
        int e0 = excl, e1 = e0 + c.x, e2 = e1 + c.y, e3 = e2 + c.z;
        *reinterpret_cast<int4*>(&offs[i0]) = make_int4(e0, e1, e2, e3);
        *reinterpret_cast<int4*>(&cur[i0])  = make_int4(e0, e1, e2, e3);
    }
}

__global__ void fill_all(const int* __restrict__ dd_s, const int* __restrict__ dd_d,
                         const int* __restrict__ pd_s, const int* __restrict__ pd_d,
                         const int* __restrict__ dp_s, const int* __restrict__ dp_d) {
    int t = blockIdx.x * blockDim.x + threadIdx.x;
    if (t < EDD) {
        int slot = atomicAdd(&g_cur_dd[__ldg(&dd_d[t])], 1);
        g_esrc_dd[slot] = __ldg(&dd_s[t]);
    } else if (t < EDD + EPD) {
        int e = t - EDD;
        int slot = atomicAdd(&g_cur_pd[__ldg(&pd_d[e])], 1);
        g_esrc_pd[slot] = __ldg(&pd_s[e]);
    } else if (t < EDD + EPD + EDP) {
        int e = t - EDD - EPD;
        int slot = atomicAdd(&g_cur_dp[__ldg(&dp_d[e])], 1);
        g_esrc_dp[slot] = __ldg(&dp_s[e]);
    }
}

// ---------------- GEMM + ReLU (proven version) ----------------
__global__ __launch_bounds__(256, 3) void agg_gemm_relu(
    const float* __restrict__ X, const float* __restrict__ Wt,
    float* __restrict__ H, int N)
{
    __shared__ float xt[DD * XTS];

    int tid = threadIdx.x;
    int row0 = blockIdx.x * 64;
    for (int j = tid; j < 64 * 32; j += 256) {
        int r = j & 63, qg = j >> 6;
        int row = row0 + r;
        float4 v = make_float4(0.f, 0.f, 0.f, 0.f);
        if (row < N) v = *reinterpret_cast<const float4*>(&X[(size_t)row * DD + qg * 4]);
        xt[(qg * 4 + 0) * XTS + r] = v.x;
        xt[(qg * 4 + 1) * XTS + r] = v.y;
        xt[(qg * 4 + 2) * XTS + r] = v.z;
        xt[(qg * 4 + 3) * XTS + r] = v.w;
    }
    __syncthreads();

    int ct = tid & 31, rt = tid >> 5;
    int c0 = ct * 4, r0 = rt * 8;
    u64 acc[4][4];
#pragma unroll
    for (int rp = 0; rp < 4; rp++)
#pragma unroll
        for (int c = 0; c < 4; c++) acc[rp][c] = 0ull;

#pragma unroll 4
    for (int k = 0; k < DD; k++) {
        float4 w = __ldg(reinterpret_cast<const float4*>(&Wt[k * DD + c0]));
        float4 xa = *reinterpret_cast<const float4*>(&xt[k * XTS + r0]);
        float4 xb = *reinterpret_cast<const float4*>(&xt[k * XTS + r0 + 4]);
        u64 xp[4] = {pk2(xa.x, xa.y), pk2(xa.z, xa.w), pk2(xb.x, xb.y), pk2(xb.z, xb.w)};
        u64 wd[4] = {dp2(w.x), dp2(w.y), dp2(w.z), dp2(w.w)};
#pragma unroll
        for (int rp = 0; rp < 4; rp++)
#pragma unroll
            for (int c = 0; c < 4; c++) fma2(acc[rp][c], xp[rp], wd[c]);
    }

#pragma unroll
    for (int rp = 0; rp < 4; rp++) {
        float lo[4], hi[4];
#pragma unroll
        for (int c = 0; c < 4; c++) up2(acc[rp][c], lo[c], hi[c]);
        int ra = row0 + r0 + 2 * rp;
        if (ra < N) {
            float4 o = make_float4(fmaxf(lo[0], 0.f), fmaxf(lo[1], 0.f),
                                   fmaxf(lo[2], 0.f), fmaxf(lo[3], 0.f));
            *reinterpret_cast<float4*>(&H[(size_t)ra * DD + c0]) = o;
        }
        if (ra + 1 < N) {
            float4 o = make_float4(fmaxf(hi[0], 0.f), fmaxf(hi[1], 0.f),
                                   fmaxf(hi[2], 0.f), fmaxf(hi[3], 0.f));
            *reinterpret_cast<float4*>(&H[(size_t)(ra + 1) * DD + c0]) = o;
        }
    }
}

// ---------------- fused drug gather: A = 0.5*(mean_dd(Hdd) + mean_pd(Hpd)) ----------------
__global__ __launch_bounds__(256) void gather_drug(
    const float* __restrict__ Hdd, const float* __restrict__ Hpd,
    const int* __restrict__ esrc_dd, const int* __restrict__ off_dd,
    const int* __restrict__ esrc_pd, const int* __restrict__ off_pd,
    float* __restrict__ A, int N)
{
    int w = (blockIdx.x * blockDim.x + threadIdx.x) >> 5;
    if (w >= N) return;
    int lane = threadIdx.x & 31;
    float4 o = make_float4(0.f, 0.f, 0.f, 0.f);
#pragma unroll
    for (int rel = 0; rel < 2; rel++) {
        const float* H = rel ? Hpd : Hdd;
        const int* esrc = rel ? esrc_pd : esrc_dd;
        const int* offs = rel ? off_pd : off_dd;
        int beg = __ldg(&offs[w]), end = __ldg(&offs[w + 1]);
        float4 acc = make_float4(0.f, 0.f, 0.f, 0.f);
        int e = beg;
        for (; e + 4 <= end; e += 4) {
            int s0 = __ldg(&esrc[e]);
            int s1 = __ldg(&esrc[e + 1]);
            int s2 = __ldg(&esrc[e + 2]);
            int s3 = __ldg(&esrc[e + 3]);
            float4 v0 = __ldg(reinterpret_cast<const float4*>(&H[(size_t)s0 * DD + lane * 4]));
            float4 v1 = __ldg(reinterpret_cast<const float4*>(&H[(size_t)s1 * DD + lane * 4]));
            float4 v2 = __ldg(reinterpret_cast<const float4*>(&H[(size_t)s2 * DD + lane * 4]));
            float4 v3 = __ldg(reinterpret_cast<const float4*>(&H[(size_t)s3 * DD + lane * 4]));
            acc.x += (v0.x + v1.x) + (v2.x + v3.x);
            acc.y += (v0.y + v1.y) + (v2.y + v3.y);
            acc.z += (v0.z + v1.z) + (v2.z + v3.z);
            acc.w += (v0.w + v1.w) + (v2.w + v3.w);
        }
        for (; e < end; e++) {
            int s = __ldg(&esrc[e]);
            float4 v = __ldg(reinterpret_cast<const float4*>(&H[(size_t)s * DD + lane * 4]));
            acc.x += v.x; acc.y += v.y; acc.z += v.z; acc.w += v.w;
        }
        float inv = 0.5f / fmaxf((float)(end - beg), 1.0f);
        o.x += acc.x * inv; o.y += acc.y * inv; o.z += acc.z * inv; o.w += acc.w * inv;
    }
    *reinterpret_cast<float4*>(&A[(size_t)w * DD + lane * 4]) = o;
}

// ---------------- prot gather (single relation, direct mean) ----------------
__global__ __launch_bounds__(256) void gather_prot(
    const float* __restrict__ H, const int* __restrict__ esrc,
    const int* __restrict__ offs, float* __restrict__ A, int N)
{
    int w = (blockIdx.x * blockDim.x + threadIdx.x) >> 5;
    if (w >= N) return;
    int lane = threadIdx.x & 31;
    int beg = __ldg(&offs[w]), end = __ldg(&offs[w + 1]);
    float4 acc = make_float4(0.f, 0.f, 0.f, 0.f);
    int e = beg;
    for (; e + 4 <= end; e += 4) {
        int s0 = __ldg(&esrc[e]);
        int s1 = __ldg(&esrc[e + 1]);
        int s2 = __ldg(&esrc[e + 2]);
        int s3 = __ldg(&esrc[e + 3]);
        float4 v0 = __ldg(reinterpret_cast<const float4*>(&H[(size_t)s0 * DD + lane * 4]));
        float4 v1 = __ldg(reinterpret_cast<const float4*>(&H[(size_t)s1 * DD + lane * 4]));
        float4 v2 = __ldg(reinterpret_cast<const float4*>(&H[(size_t)s2 * DD + lane * 4]));
        float4 v3 = __ldg(reinterpret_cast<const float4*>(&H[(size_t)s3 * DD + lane * 4]));
        acc.x += (v0.x + v1.x) + (v2.x + v3.x);
        acc.y += (v0.y + v1.y) + (v2.y + v3.y);
        acc.z += (v0.z + v1.z) + (v2.z + v3.z);
        acc.w += (v0.w + v1.w) + (v2.w + v3.w);
    }
    for (; e < end; e++) {
        int s = __ldg(&esrc[e]);
        float4 v = __ldg(reinterpret_cast<const float4*>(&H[(size_t)s * DD + lane * 4]));
        acc.x += v.x; acc.y += v.y; acc.z += v.z; acc.w += v.w;
    }
    float inv = 1.0f / fmaxf((float)(end - beg), 1.0f);
    *reinterpret_cast<float4*>(&A[(size_t)w * DD + lane * 4]) =
        make_float4(acc.x * inv, acc.y * inv, acc.z * inv, acc.w * inv);
}

// ---------------- fused node update (proven version) ----------------
__global__ __launch_bounds__(256, 2) void node_update(
    const float* __restrict__ X,
    const float* __restrict__ A,
    const float* __restrict__ Wt,
    const float* __restrict__ b,
    const float* __restrict__ g,
    const float* __restrict__ be,
    float* __restrict__ out, int N)
{
    __shared__ float xt[DD * XTS];
    __shared__ float at[DD * XTS];

    int tid = threadIdx.x;
    int row0 = blockIdx.x * 64;
    for (int j = tid; j < 64 * 32; j += 256) {
        int r = j & 63, qg = j >> 6;
        int row = row0 + r;
        float4 xv = make_float4(0.f, 0.f, 0.f, 0.f);
        float4 av = make_float4(0.f, 0.f, 0.f, 0.f);
        if (row < N) {
            xv = *reinterpret_cast<const float4*>(&X[(size_t)row * DD + qg * 4]);
            av = *reinterpret_cast<const float4*>(&A[(size_t)row * DD + qg * 4]);
        }
        xt[(qg * 4 + 0) * XTS + r] = xv.x;
        xt[(qg * 4 + 1) * XTS + r] = xv.y;
        xt[(qg * 4 + 2) * XTS + r] = xv.z;
        xt[(qg * 4 + 3) * XTS + r] = xv.w;
        at[(qg * 4 + 0) * XTS + r] = av.x;
        at[(qg * 4 + 1) * XTS + r] = av.y;
        at[(qg * 4 + 2) * XTS + r] = av.z;
        at[(qg * 4 + 3) * XTS + r] = av.w;
    }
    __syncthreads();

    int ct = tid & 31, rt = tid >> 5;
    int c0 = ct * 4, r0 = rt * 8;
    u64 acc[4][4];
#pragma unroll
    for (int rp = 0; rp < 4; rp++)
#pragma unroll
        for (int c = 0; c < 4; c++) acc[rp][c] = 0ull;

#pragma unroll 2
    for (int k = 0; k < DD; k++) {
        float4 w1 = __ldg(reinterpret_cast<const float4*>(&Wt[k * 256 + c0]));
        float4 w2 = __ldg(reinterpret_cast<const float4*>(&Wt[k * 256 + 128 + c0]));
        float4 xa = *reinterpret_cast<const float4*>(&xt[k * XTS + r0]);
        float4 xb = *reinterpret_cast<const float4*>(&xt[k * XTS + r0 + 4]);
        float4 aa = *reinterpret_cast<const float4*>(&at[k * XTS + r0]);
        float4 ab = *reinterpret_cast<const float4*>(&at[k * XTS + r0 + 4]);
        u64 xp[4] = {pk2(xa.x, xa.y), pk2(xa.z, xa.w), pk2(xb.x, xb.y), pk2(xb.z, xb.w)};
        u64 ap[4] = {pk2(aa.x, aa.y), pk2(aa.z, aa.w), pk2(ab.x, ab.y), pk2(ab.z, ab.w)};
        u64 w1d[4] = {dp2(w1.x), dp2(w1.y), dp2(w1.z), dp2(w1.w)};
        u64 w2d[4] = {dp2(w2.x), dp2(w2.y), dp2(w2.z), dp2(w2.w)};
#pragma unroll
        for (int rp = 0; rp < 4; rp++)
#pragma unroll
            for (int c = 0; c < 4; c++) {
                fma2(acc[rp][c], xp[rp], w1d[c]);
                fma2(acc[rp][c], ap[rp], w2d[c]);
            }
    }
    float4 bb = *reinterpret_cast<const float4*>(&b[c0]);
    __syncthreads();
    float* hs = xt;

#pragma unroll
    for (int rp = 0; rp < 4; rp++) {
        float lo[4], hi[4];
#pragma unroll
        for (int c = 0; c < 4; c++) up2(acc[rp][c], lo[c], hi[c]);
        int rla = r0 + 2 * rp;
        int ra = row0 + rla;
        float4 xra = make_float4(0.f, 0.f, 0.f, 0.f);
        float4 xrb = make_float4(0.f, 0.f, 0.f, 0.f);
        if (ra < N)     xra = *reinterpret_cast<const float4*>(&X[(size_t)ra * DD + c0]);
        if (ra + 1 < N) xrb = *reinterpret_cast<const float4*>(&X[(size_t)(ra + 1) * DD + c0]);
        float4 oa, ob;
        oa.x = fmaxf(lo[0] + bb.x, 0.f) + xra.x;
        oa.y = fmaxf(lo[1] + bb.y, 0.f) + xra.y;
        oa.z = fmaxf(lo[2] + bb.z, 0.f) + xra.z;
        oa.w = fmaxf(lo[3] + bb.w, 0.f) + xra.w;
        ob.x = fmaxf(hi[0] + bb.x, 0.f) + xrb.x;
        ob.y = fmaxf(hi[1] + bb.y, 0.f) + xrb.y;
        ob.z = fmaxf(hi[2] + bb.z, 0.f) + xrb.z;
        ob.w = fmaxf(hi[3] + bb.w, 0.f) + xrb.w;
        *reinterpret_cast<float4*>(&hs[rla * DD + c0]) = oa;
        *reinterpret_cast<float4*>(&hs[(rla + 1) * DD + c0]) = ob;
    }
    __syncthreads();

    int lane = tid & 31;
    float4 gg  = *reinterpret_cast<const float4*>(&g[lane * 4]);
    float4 bev = *reinterpret_cast<const float4*>(&be[lane * 4]);
    for (int r = 0; r < 8; r++) {
        int rl = rt * 8 + r;
        int row = row0 + rl;
        float4 v = *reinterpret_cast<const float4*>(&hs[rl * DD + lane * 4]);
        float s  = v.x + v.y + v.z + v.w;
        float s2 = v.x * v.x + v.y * v.y + v.z * v.z + v.w * v.w;
#pragma unroll
        for (int o_ = 16; o_; o_ >>= 1) {
            s  += __shfl_xor_sync(0xFFFFFFFFu, s, o_);
            s2 += __shfl_xor_sync(0xFFFFFFFFu, s2, o_);
        }
        float mu  = s * (1.0f / 128.0f);
        float var = s2 * (1.0f / 128.0f) - mu * mu;
        float rstd = rsqrtf(var + 1e-5f);
        if (row < N) {
            float4 o;
            o.x = (v.x - mu) * rstd * gg.x + bev.x;
            o.y = (v.y - mu) * rstd * gg.y + bev.y;
            o.z = (v.z - mu) * rstd * gg.z + bev.z;
            o.w = (v.w - mu) * rstd * gg.w + bev.w;
            *reinterpret_cast<float4*>(&out[(size_t)row * DD + lane * 4]) = o;
        }
    }
}

// ---------------- launch: R12 three-branch DAG + split weight prep ----------------
extern "C" void kernel_launch(void* const* d_in, const int* in_sizes, int n_in,
                              void* d_out, int out_size)
{
    const float* x_drug  = (const float*)d_in[0];
    const float* x_prot  = (const float*)d_in[1];
    const float* Wagg_dd = (const float*)d_in[2];
    const float* Wagg_dp = (const float*)d_in[3];
    const float* Wagg_pd = (const float*)d_in[4];
    const float* W_drug  = (const float*)d_in[5];
    const float* b_drug  = (const float*)d_in[6];
    const float* W_prot  = (const float*)d_in[7];
    const float* b_prot  = (const float*)d_in[8];
    const float* g_drug  = (const float*)d_in[9];
    const float* be_drug = (const float*)d_in[10];
    const float* g_prot  = (const float*)d_in[11];
    const float* be_prot = (const float*)d_in[12];
    const int* dd_src = (const int*)d_in[13];
    const int* dd_dst = (const int*)d_in[14];
    const int* dp_src = (const int*)d_in[15];
    const int* dp_dst = (const int*)d_in[16];
    const int* pd_src = (const int*)d_in[17];
    const int* pd_dst = (const int*)d_in[18];
    float* out = (float*)d_out;

    float *Hdd, *Hdp, *Hpd, *Adrug, *Aprot;
    float *WtDD, *WtDP, *WtPD, *WtDR, *WtPR;
    int *off_dd, *off_pd, *off_dp, *esrc_dd, *esrc_pd, *esrc_dp;
    cudaGetSymbolAddress((void**)&Hdd, g_Hdd);
    cudaGetSymbolAddress((void**)&Hdp, g_Hdp);
    cudaGetSymbolAddress((void**)&Hpd, g_Hpd);
    cudaGetSymbolAddress((void**)&Adrug, g_Adrug);
    cudaGetSymbolAddress((void**)&Aprot, g_Aprot);
    cudaGetSymbolAddress((void**)&WtDD, g_WtDD);
    cudaGetSymbolAddress((void**)&WtDP, g_WtDP);
    cudaGetSymbolAddress((void**)&WtPD, g_WtPD);
    cudaGetSymbolAddress((void**)&WtDR, g_WtDR);
    cudaGetSymbolAddress((void**)&WtPR, g_WtPR);
    cudaGetSymbolAddress((void**)&off_dd, g_off_dd);
    cudaGetSymbolAddress((void**)&off_pd, g_off_pd);
    cudaGetSymbolAddress((void**)&off_dp, g_off_dp);
    cudaGetSymbolAddress((void**)&esrc_dd, g_esrc_dd);
    cudaGetSymbolAddress((void**)&esrc_pd, g_esrc_pd);
    cudaGetSymbolAddress((void**)&esrc_dp, g_esrc_dp);

    cudaStream_t s1 = g_res.s1;
    cudaStream_t s2 = g_res.s2;

    // ---- fork s1/s2 off the main stream ----
    cudaEventRecord(g_res.eFork, 0);
    cudaStreamWaitEvent(s1, g_res.eFork, 0);
    cudaStreamWaitEvent(s2, g_res.eFork, 0);

    // ---- s2: node-weight transpose first (off critical path) ----
    prep_node<<<128, 256, 0, s2>>>(W_drug, W_prot);
    cudaEventRecord(g_res.ePrepN, s2);

    // ---- s1: CSR build chain ----
    zero_counts<<<256, 256, 0, s1>>>();
    count_all<<<(EDD + EPD + EDP + 255) / 256, 256, 0, s1>>>(dd_dst, pd_dst, dp_dst);
    chunk_sums<<<NCH_TOT, 1024, 0, s1>>>();
    scan_partials<<<1, 64, 0, s1>>>();
    chunk_scan<<<NCH_TOT, 1024, 0, s1>>>();
    fill_all<<<(EDD + EPD + EDP + 255) / 256, 256, 0, s1>>>(dd_src, dd_dst, pd_src, pd_dst, dp_src, dp_dst);
    cudaEventRecord(g_res.eFill, s1);

    // ---- s0: agg-weight transpose + drug/prot aggs ----
    prep_agg<<<64, 256>>>(Wagg_dd, Wagg_dp, Wagg_pd);
    cudaEventRecord(g_res.ePrepA, 0);
    agg_gemm_relu<<<(NDRUG + 63) / 64, 256>>>(x_drug, WtDD, Hdd, NDRUG);
    agg_gemm_relu<<<(NPROT + 63) / 64, 256>>>(x_prot, WtPD, Hpd, NPROT);
    cudaEventRecord(g_res.ePD, 0);

    // ---- s2: drug->prot branch (after prep_node on s2; needs WtDP from s0 prep) ----
    cudaStreamWaitEvent(s2, g_res.ePrepA, 0);
    agg_gemm_relu<<<(NDRUG + 63) / 64, 256, 0, s2>>>(x_drug, WtDP, Hdp, NDRUG);
    cudaStreamWaitEvent(s2, g_res.eFill, 0);
    gather_prot<<<(NPROT * 32 + 255) / 256, 256, 0, s2>>>(Hdp, esrc_dp, off_dp, Aprot, NPROT);
    node_update<<<(NPROT + 63) / 64, 256, 0, s2>>>(
        x_prot, Aprot, WtPR, b_prot, g_prot, be_prot,
        out + (size_t)NDRUG * DD, NPROT);
    cudaEventRecord(g_res.eEnd2, s2);

    // ---- s1: fused drug gather (needs Hdd + Hpd via ePD + CSR on s1) ----
    cudaStreamWaitEvent(s1, g_res.ePD, 0);
    gather_drug<<<(NDRUG * 32 + 255) / 256, 256, 0, s1>>>(
        Hdd, Hpd, esrc_dd, off_dd, esrc_pd, off_pd, Adrug, NDRUG);
    cudaEventRecord(g_res.eGD, s1);

    // ---- s0: drug node update (needs Adrug + WtDR), then join ----
    cudaStreamWaitEvent(0, g_res.eGD, 0);
    cudaStreamWaitEvent(0, g_res.ePrepN, 0);
    node_update<<<(NDRUG + 63) / 64, 256>>>(
        x_drug, Adrug, WtDR, b_drug, g_drug, be_drug, out, NDRUG);
    cudaStreamWaitEvent(0, g_res.eEnd2, 0);
}

// round 17
// speedup vs baseline: 1.0639x; 1.0389x over previous
#include <cuda_runtime.h>
#include <cuda_fp16.h>
#include <cstdint>

#define NDRUG 100000
#define NPROT 50000
#define EDD 800000
#define EDP 600000
#define EPD 600000
#define DD 128
#define XTS 68

// chunked scan geometry
#define CH 4096
#define NCH_DD 25
#define NCH_PD 25
#define NCH_DP 13
#define NCH_TOT (NCH_DD + NCH_PD + NCH_DP)   // 63

typedef unsigned long long u64;

__device__ __forceinline__ u64 pk2(float lo, float hi) {
    u64 r; asm("mov.b64 %0,{%1,%2};" : "=l"(r) : "f"(lo), "f"(hi)); return r;
}
__device__ __forceinline__ u64 dp2(float v) {
    u64 r; asm("mov.b64 %0,{%1,%1};" : "=l"(r) : "f"(v)); return r;
}
__device__ __forceinline__ void fma2(u64& d, u64 a, u64 b) {
    asm("fma.rn.f32x2 %0,%1,%2,%3;" : "=l"(d) : "l"(a), "l"(b), "l"(d));
}
__device__ __forceinline__ void up2(u64 v, float& lo, float& hi) {
    asm("mov.b64 {%0,%1},%2;" : "=f"(lo), "=f"(hi) : "l"(v));
}

// ---------------- scratch ----------------
// H buffers in fp16: row = 128 halfs = 32 uint2
__device__ __align__(16) __half g_Hdd[(size_t)NDRUG * DD];
__device__ __align__(16) __half g_Hdp[(size_t)NDRUG * DD];
__device__ __align__(16) __half g_Hpd[(size_t)NPROT * DD];
__device__ __align__(16) float g_Adrug[(size_t)NDRUG * DD];
__device__ __align__(16) float g_Aprot[(size_t)NPROT * DD];
// CSR
__device__ __align__(16) int g_cnt_dd[NDRUG];
__device__ __align__(16) int g_cnt_pd[NDRUG];
__device__ __align__(16) int g_cnt_dp[NPROT];
__device__ __align__(16) int g_off_dd[NDRUG + 4];
__device__ __align__(16) int g_off_pd[NDRUG + 4];
__device__ __align__(16) int g_off_dp[NPROT + 4];
__device__ __align__(16) int g_cur_dd[NDRUG + 4];
__device__ __align__(16) int g_cur_pd[NDRUG + 4];
__device__ __align__(16) int g_cur_dp[NPROT + 4];
__device__ int g_esrc_dd[EDD];
__device__ int g_esrc_pd[EPD];
__device__ int g_esrc_dp[EDP];
__device__ int g_part[NCH_TOT];
__device__ int g_pbase[NCH_TOT];
// transposed weights
__device__ __align__(16) float g_WtDD[DD * DD];
__device__ __align__(16) float g_WtDP[DD * DD];
__device__ __align__(16) float g_WtPD[DD * DD];
__device__ __align__(16) float g_WtDR[DD * 2 * DD];
__device__ __align__(16) float g_WtPR[DD * 2 * DD];

// ---------------- host-side stream/event resources ----------------
struct GpuRes {
    cudaStream_t s1, s2;
    cudaEvent_t eFork, ePrep, eDD, ePD, eFill, eGD, eEnd2;
    GpuRes() {
        cudaStreamCreateWithFlags(&s1, cudaStreamNonBlocking);
        cudaStreamCreateWithFlags(&s2, cudaStreamNonBlocking);
        cudaEventCreateWithFlags(&eFork, cudaEventDisableTiming);
        cudaEventCreateWithFlags(&ePrep, cudaEventDisableTiming);
        cudaEventCreateWithFlags(&eDD,   cudaEventDisableTiming);
        cudaEventCreateWithFlags(&ePD,   cudaEventDisableTiming);
        cudaEventCreateWithFlags(&eFill, cudaEventDisableTiming);
        cudaEventCreateWithFlags(&eGD,   cudaEventDisableTiming);
        cudaEventCreateWithFlags(&eEnd2, cudaEventDisableTiming);
    }
};
static GpuRes g_res;

// ---------------- weight transpose ----------------
__global__ void prep_weights(const float* __restrict__ Wdd, const float* __restrict__ Wdp,
                             const float* __restrict__ Wpd, const float* __restrict__ Wdr,
                             const float* __restrict__ Wpr)
{
    int t = blockIdx.x * blockDim.x + threadIdx.x;
    int stride = gridDim.x * blockDim.x;
    for (int i = t; i < DD * DD; i += stride) {
        int c = i >> 7, k = i & 127;
        g_WtDD[k * DD + c] = Wdd[i];
        g_WtDP[k * DD + c] = Wdp[i];
        g_WtPD[k * DD + c] = Wpd[i];
    }
    for (int i = t; i < DD * 2 * DD; i += stride) {
        int c = i >> 8, col = i & 255;
        int k = col & 127, half = col >> 7;
        g_WtDR[k * 256 + half * 128 + c] = Wdr[i];
        g_WtPR[k * 256 + half * 128 + c] = Wpr[i];
    }
}

// ---------------- CSR build ----------------
__global__ void zero_counts() {
    int t = blockIdx.x * blockDim.x + threadIdx.x;
    int stride = gridDim.x * blockDim.x;
    for (int i = t; i < NDRUG; i += stride) { g_cnt_dd[i] = 0; g_cnt_pd[i] = 0; }
    for (int i = t; i < NPROT; i += stride) g_cnt_dp[i] = 0;
}

__global__ void count_all(const int* __restrict__ dd, const int* __restrict__ pd,
                          const int* __restrict__ dp) {
    int t = blockIdx.x * blockDim.x + threadIdx.x;
    if (t < EDD) atomicAdd(&g_cnt_dd[__ldg(&dd[t])], 1);
    else if (t < EDD + EPD) atomicAdd(&g_cnt_pd[__ldg(&pd[t - EDD])], 1);
    else if (t < EDD + EPD + EDP) atomicAdd(&g_cnt_dp[__ldg(&dp[t - EDD - EPD])], 1);
}

__device__ __forceinline__ void chunk_map(int b, const int*& cnt, int*& offs, int*& cur,
                                          int& base, int& n) {
    if (b < NCH_DD)              { cnt = g_cnt_dd; offs = g_off_dd; cur = g_cur_dd; base = b * CH; n = NDRUG; }
    else if (b < NCH_DD + NCH_PD){ cnt = g_cnt_pd; offs = g_off_pd; cur = g_cur_pd; base = (b - NCH_DD) * CH; n = NDRUG; }
    else                         { cnt = g_cnt_dp; offs = g_off_dp; cur = g_cur_dp; base = (b - NCH_DD - NCH_PD) * CH; n = NPROT; }
}

__global__ __launch_bounds__(1024) void chunk_sums() {
    const int* cnt; int* offs; int* cur; int base, n;
    chunk_map(blockIdx.x, cnt, offs, cur, base, n);
    int i0 = base + threadIdx.x * 4;
    int4 c = make_int4(0, 0, 0, 0);
    if (i0 < n) c = *reinterpret_cast<const int4*>(&cnt[i0]);
    int tot = c.x + c.y + c.z + c.w;
    __shared__ int ws[32];
    int lane = threadIdx.x & 31, wid = threadIdx.x >> 5;
#pragma unroll
    for (int o = 16; o; o >>= 1) tot += __shfl_xor_sync(0xFFFFFFFFu, tot, o);
    if (lane == 0) ws[wid] = tot;
    __syncthreads();
    if (wid == 0) {
        int v = ws[lane];
#pragma unroll
        for (int o = 16; o; o >>= 1) v += __shfl_xor_sync(0xFFFFFFFFu, v, o);
        if (lane == 0) g_part[blockIdx.x] = v;
    }
}

__global__ void scan_partials() {
    __shared__ int s[64];
    int t = threadIdx.x;
    int v = (t < NCH_TOT) ? g_part[t] : 0;
    s[t] = v;
    __syncthreads();
#pragma unroll
    for (int o = 1; o < 64; o <<= 1) {
        int add = (t >= o) ? s[t - o] : 0;
        __syncthreads();
        s[t] += add;
        __syncthreads();
    }
    if (t < NCH_TOT) {
        int excl = s[t] - v;
        int segoff = (t >= NCH_DD + NCH_PD) ? (EDD + EPD) : (t >= NCH_DD ? EDD : 0);
        g_pbase[t] = excl - segoff;
    }
    if (t == 0) {
        g_off_dd[NDRUG] = EDD;
        g_off_pd[NDRUG] = EPD;
        g_off_dp[NPROT] = EDP;
    }
}

__global__ __launch_bounds__(1024) void chunk_scan() {
    const int* cnt; int* offs; int* cur; int base, n;
    chunk_map(blockIdx.x, cnt, offs, cur, base, n);
    int carry = g_pbase[blockIdx.x];
    __shared__ int wsum[32];
    int tid = threadIdx.x, lane = tid & 31, wid = tid >> 5;
    int i0 = base + tid * 4;
    int4 c = make_int4(0, 0, 0, 0);
    if (i0 < n) c = *reinterpret_cast<const int4*>(&cnt[i0]);
    int tot = c.x + c.y + c.z + c.w;
    int incl = tot;
#pragma unroll
    for (int o = 1; o < 32; o <<= 1) {
        int v = __shfl_up_sync(0xFFFFFFFFu, incl, o);
        if (lane >= o) incl += v;
    }
    if (lane == 31) wsum[wid] = incl;
    __syncthreads();
    if (wid == 0) {
        int v = wsum[lane];
        int wincl = v;
#pragma unroll
        for (int o = 1; o < 32; o <<= 1) {
            int t2 = __shfl_up_sync(0xFFFFFFFFu, wincl, o);
            if (lane >= o) wincl += t2;
        }
        wsum[lane] = wincl - v;
    }
    __syncthreads();
    int excl = carry + wsum[wid] + incl - tot;
    if (i0 < n) {
        int e0 = excl, e1 = e0 + c.x, e2 = e1 + c.y, e3 = e2 + c.z;
        *reinterpret_cast<int4*>(&offs[i0]) = make_int4(e0, e1, e2, e3);
        *reinterpret_cast<int4*>(&cur[i0])  = make_int4(e0, e1, e2, e3);
    }
}

__global__ void fill_all(const int* __restrict__ dd_s, const int* __restrict__ dd_d,
                         const int* __restrict__ pd_s, const int* __restrict__ pd_d,
                         const int* __restrict__ dp_s, const int* __restrict__ dp_d) {
    int t = blockIdx.x * blockDim.x + threadIdx.x;
    if (t < EDD) {
        int slot = atomicAdd(&g_cur_dd[__ldg(&dd_d[t])], 1);
        g_esrc_dd[slot] = __ldg(&dd_s[t]);
    } else if (t < EDD + EPD) {
        int e = t - EDD;
        int slot = atomicAdd(&g_cur_pd[__ldg(&pd_d[e])], 1);
        g_esrc_pd[slot] = __ldg(&pd_s[e]);
    } else if (t < EDD + EPD + EDP) {
        int e = t - EDD - EPD;
        int slot = atomicAdd(&g_cur_dp[__ldg(&dp_d[e])], 1);
        g_esrc_dp[slot] = __ldg(&dp_s[e]);
    }
}

// ---------------- GEMM + ReLU (proven core; fp16 H store) ----------------
__global__ __launch_bounds__(256, 3) void agg_gemm_relu(
    const float* __restrict__ X, const float* __restrict__ Wt,
    __half* __restrict__ H, int N)
{
    __shared__ float xt[DD * XTS];

    int tid = threadIdx.x;
    int row0 = blockIdx.x * 64;
    for (int j = tid; j < 64 * 32; j += 256) {
        int r = j & 63, qg = j >> 6;
        int row = row0 + r;
        float4 v = make_float4(0.f, 0.f, 0.f, 0.f);
        if (row < N) v = *reinterpret_cast<const float4*>(&X[(size_t)row * DD + qg * 4]);
        xt[(qg * 4 + 0) * XTS + r] = v.x;
        xt[(qg * 4 + 1) * XTS + r] = v.y;
        xt[(qg * 4 + 2) * XTS + r] = v.z;
        xt[(qg * 4 + 3) * XTS + r] = v.w;
    }
    __syncthreads();

    int ct = tid & 31, rt = tid >> 5;
    int c0 = ct * 4, r0 = rt * 8;
    u64 acc[4][4];
#pragma unroll
    for (int rp = 0; rp < 4; rp++)
#pragma unroll
        for (int c = 0; c < 4; c++) acc[rp][c] = 0ull;

#pragma unroll 4
    for (int k = 0; k < DD; k++) {
        float4 w = __ldg(reinterpret_cast<const float4*>(&Wt[k * DD + c0]));
        float4 xa = *reinterpret_cast<const float4*>(&xt[k * XTS + r0]);
        float4 xb = *reinterpret_cast<const float4*>(&xt[k * XTS + r0 + 4]);
        u64 xp[4] = {pk2(xa.x, xa.y), pk2(xa.z, xa.w), pk2(xb.x, xb.y), pk2(xb.z, xb.w)};
        u64 wd[4] = {dp2(w.x), dp2(w.y), dp2(w.z), dp2(w.w)};
#pragma unroll
        for (int rp = 0; rp < 4; rp++)
#pragma unroll
            for (int c = 0; c < 4; c++) fma2(acc[rp][c], xp[rp], wd[c]);
    }

    uint2* Hv = reinterpret_cast<uint2*>(H);
#pragma unroll
    for (int rp = 0; rp < 4; rp++) {
        float lo[4], hi[4];
#pragma unroll
        for (int c = 0; c < 4; c++) up2(acc[rp][c], lo[c], hi[c]);
        int ra = row0 + r0 + 2 * rp;
        if (ra < N) {
            __half2 ha = __floats2half2_rn(fmaxf(lo[0], 0.f), fmaxf(lo[1], 0.f));
            __half2 hb = __floats2half2_rn(fmaxf(lo[2], 0.f), fmaxf(lo[3], 0.f));
            uint2 raw;
            raw.x = *reinterpret_cast<uint32_t*>(&ha);
            raw.y = *reinterpret_cast<uint32_t*>(&hb);
            Hv[(size_t)ra * 32 + ct] = raw;
        }
        if (ra + 1 < N) {
            __half2 ha = __floats2half2_rn(fmaxf(hi[0], 0.f), fmaxf(hi[1], 0.f));
            __half2 hb = __floats2half2_rn(fmaxf(hi[2], 0.f), fmaxf(hi[3], 0.f));
            uint2 raw;
            raw.x = *reinterpret_cast<uint32_t*>(&ha);
            raw.y = *reinterpret_cast<uint32_t*>(&hb);
            Hv[(size_t)(ra + 1) * 32 + ct] = raw;
        }
    }
}

// ---------------- fp16 H row accumulate (per-lane 4 cols via one uint2) ----------------
__device__ __forceinline__ void acc_h16(
    const uint2* __restrict__ Hv, int s, int lane, float4& acc)
{
    uint2 raw = __ldg(&Hv[(size_t)s * 32 + lane]);
    __half2 ha = *reinterpret_cast<__half2*>(&raw.x);
    __half2 hb = *reinterpret_cast<__half2*>(&raw.y);
    float2 f0 = __half22float2(ha);
    float2 f1 = __half22float2(hb);
    acc.x += f0.x; acc.y += f0.y; acc.z += f1.x; acc.w += f1.y;
}

// ---------------- fused drug gather: A = 0.5*(mean_dd(Hdd) + mean_pd(Hpd)) ----------------
__global__ __launch_bounds__(256) void gather_drug(
    const __half* __restrict__ Hdd, const __half* __restrict__ Hpd,
    const int* __restrict__ esrc_dd, const int* __restrict__ off_dd,
    const int* __restrict__ esrc_pd, const int* __restrict__ off_pd,
    float* __restrict__ A, int N)
{
    int w = (blockIdx.x * blockDim.x + threadIdx.x) >> 5;
    if (w >= N) return;
    int lane = threadIdx.x & 31;
    float4 o = make_float4(0.f, 0.f, 0.f, 0.f);
#pragma unroll
    for (int rel = 0; rel < 2; rel++) {
        const uint2* Hv = reinterpret_cast<const uint2*>(rel ? Hpd : Hdd);
        const int* esrc = rel ? esrc_pd : esrc_dd;
        const int* offs = rel ? off_pd : off_dd;
        int beg = __ldg(&offs[w]), end = __ldg(&offs[w + 1]);
        float4 acc = make_float4(0.f, 0.f, 0.f, 0.f);
        int e = beg;
        for (; e + 4 <= end; e += 4) {
            int s0 = __ldg(&esrc[e]);
            int s1 = __ldg(&esrc[e + 1]);
            int s2 = __ldg(&esrc[e + 2]);
            int s3 = __ldg(&esrc[e + 3]);
            acc_h16(Hv, s0, lane, acc);
            acc_h16(Hv, s1, lane, acc);
            acc_h16(Hv, s2, lane, acc);
            acc_h16(Hv, s3, lane, acc);
        }
        for (; e < end; e++) {
            int s = __ldg(&esrc[e]);
            acc_h16(Hv, s, lane, acc);
        }
        float inv = 0.5f / fmaxf((float)(end - beg), 1.0f);
        o.x += acc.x * inv; o.y += acc.y * inv; o.z += acc.z * inv; o.w += acc.w * inv;
    }
    *reinterpret_cast<float4*>(&A[(size_t)w * DD + lane * 4]) = o;
}

// ---------------- prot gather (single relation, direct mean) ----------------
__global__ __launch_bounds__(256) void gather_prot(
    const __half* __restrict__ H, const int* __restrict__ esrc,
    const int* __restrict__ offs, float* __restrict__ A, int N)
{
    int w = (blockIdx.x * blockDim.x + threadIdx.x) >> 5;
    if (w >= N) return;
    int lane = threadIdx.x & 31;
    const uint2* Hv = reinterpret_cast<const uint2*>(H);
    int beg = __ldg(&offs[w]), end = __ldg(&offs[w + 1]);
    float4 acc = make_float4(0.f, 0.f, 0.f, 0.f);
    int e = beg;
    for (; e + 4 <= end; e += 4) {
        int s0 = __ldg(&esrc[e]);
        int s1 = __ldg(&esrc[e + 1]);
        int s2 = __ldg(&esrc[e + 2]);
        int s3 = __ldg(&esrc[e + 3]);
        acc_h16(Hv, s0, lane, acc);
        acc_h16(Hv, s1, lane, acc);
        acc_h16(Hv, s2, lane, acc);
        acc_h16(Hv, s3, lane, acc);
    }
    for (; e < end; e++) {
        int s = __ldg(&esrc[e]);
        acc_h16(Hv, s, lane, acc);
    }
    float inv = 1.0f / fmaxf((float)(end - beg), 1.0f);
    *reinterpret_cast<float4*>(&A[(size_t)w * DD + lane * 4]) =
        make_float4(acc.x * inv, acc.y * inv, acc.z * inv, acc.w * inv);
}

// ---------------- fused node update (proven version) ----------------
__global__ __launch_bounds__(256, 2) void node_update(
    const float* __restrict__ X,
    const float* __restrict__ A,
    const float* __restrict__ Wt,
    const float* __restrict__ b,
    const float* __restrict__ g,
    const float* __restrict__ be,
    float* __restrict__ out, int N)
{
    __shared__ float xt[DD * XTS];
    __shared__ float at[DD * XTS];

    int tid = threadIdx.x;
    int row0 = blockIdx.x * 64;
    for (int j = tid; j < 64 * 32; j += 256) {
        int r = j & 63, qg = j >> 6;
        int row = row0 + r;
        float4 xv = make_float4(0.f, 0.f, 0.f, 0.f);
        float4 av = make_float4(0.f, 0.f, 0.f, 0.f);
        if (row < N) {
            xv = *reinterpret_cast<const float4*>(&X[(size_t)row * DD + qg * 4]);
            av = *reinterpret_cast<const float4*>(&A[(size_t)row * DD + qg * 4]);
        }
        xt[(qg * 4 + 0) * XTS + r] = xv.x;
        xt[(qg * 4 + 1) * XTS + r] = xv.y;
        xt[(qg * 4 + 2) * XTS + r] = xv.z;
        xt[(qg * 4 + 3) * XTS + r] = xv.w;
        at[(qg * 4 + 0) * XTS + r] = av.x;
        at[(qg * 4 + 1) * XTS + r] = av.y;
        at[(qg * 4 + 2) * XTS + r] = av.z;
        at[(qg * 4 + 3) * XTS + r] = av.w;
    }
    __syncthreads();

    int ct = tid & 31, rt = tid >> 5;
    int c0 = ct * 4, r0 = rt * 8;
    u64 acc[4][4];
#pragma unroll
    for (int rp = 0; rp < 4; rp++)
#pragma unroll
        for (int c = 0; c < 4; c++) acc[rp][c] = 0ull;

#pragma unroll 2
    for (int k = 0; k < DD; k++) {
        float4 w1 = __ldg(reinterpret_cast<const float4*>(&Wt[k * 256 + c0]));
        float4 w2 = __ldg(reinterpret_cast<const float4*>(&Wt[k * 256 + 128 + c0]));
        float4 xa = *reinterpret_cast<const float4*>(&xt[k * XTS + r0]);
        float4 xb = *reinterpret_cast<const float4*>(&xt[k * XTS + r0 + 4]);
        float4 aa = *reinterpret_cast<const float4*>(&at[k * XTS + r0]);
        float4 ab = *reinterpret_cast<const float4*>(&at[k * XTS + r0 + 4]);
        u64 xp[4] = {pk2(xa.x, xa.y), pk2(xa.z, xa.w), pk2(xb.x, xb.y), pk2(xb.z, xb.w)};
        u64 ap[4] = {pk2(aa.x, aa.y), pk2(aa.z, aa.w), pk2(ab.x, ab.y), pk2(ab.z, ab.w)};
        u64 w1d[4] = {dp2(w1.x), dp2(w1.y), dp2(w1.z), dp2(w1.w)};
        u64 w2d[4] = {dp2(w2.x), dp2(w2.y), dp2(w2.z), dp2(w2.w)};
#pragma unroll
        for (int rp = 0; rp < 4; rp++)
#pragma unroll
            for (int c = 0; c < 4; c++) {
                fma2(acc[rp][c], xp[rp], w1d[c]);
                fma2(acc[rp][c], ap[rp], w2d[c]);
            }
    }
    float4 bb = *reinterpret_cast<const float4*>(&b[c0]);
    __syncthreads();
    float* hs = xt;

#pragma unroll
    for (int rp = 0; rp < 4; rp++) {
        float lo[4], hi[4];
#pragma unroll
        for (int c = 0; c < 4; c++) up2(acc[rp][c], lo[c], hi[c]);
        int rla = r0 + 2 * rp;
        int ra = row0 + rla;
        float4 xra = make_float4(0.f, 0.f, 0.f, 0.f);
        float4 xrb = make_float4(0.f, 0.f, 0.f, 0.f);
        if (ra < N)     xra = *reinterpret_cast<const float4*>(&X[(size_t)ra * DD + c0]);
        if (ra + 1 < N) xrb = *reinterpret_cast<const float4*>(&X[(size_t)(ra + 1) * DD + c0]);
        float4 oa, ob;
        oa.x = fmaxf(lo[0] + bb.x, 0.f) + xra.x;
        oa.y = fmaxf(lo[1] + bb.y, 0.f) + xra.y;
        oa.z = fmaxf(lo[2] + bb.z, 0.f) + xra.z;
        oa.w = fmaxf(lo[3] + bb.w, 0.f) + xra.w;
        ob.x = fmaxf(hi[0] + bb.x, 0.f) + xrb.x;
        ob.y = fmaxf(hi[1] + bb.y, 0.f) + xrb.y;
        ob.z = fmaxf(hi[2] + bb.z, 0.f) + xrb.z;
        ob.w = fmaxf(hi[3] + bb.w, 0.f) + xrb.w;
        *reinterpret_cast<float4*>(&hs[rla * DD + c0]) = oa;
        *reinterpret_cast<float4*>(&hs[(rla + 1) * DD + c0]) = ob;
    }
    __syncthreads();

    int lane = tid & 31;
    float4 gg  = *reinterpret_cast<const float4*>(&g[lane * 4]);
    float4 bev = *reinterpret_cast<const float4*>(&be[lane * 4]);
    for (int r = 0; r < 8; r++) {
        int rl = rt * 8 + r;
        int row = row0 + rl;
        float4 v = *reinterpret_cast<const float4*>(&hs[rl * DD + lane * 4]);
        float s  = v.x + v.y + v.z + v.w;
        float s2 = v.x * v.x + v.y * v.y + v.z * v.z + v.w * v.w;
#pragma unroll
        for (int o_ = 16; o_; o_ >>= 1) {
            s  += __shfl_xor_sync(0xFFFFFFFFu, s, o_);
            s2 += __shfl_xor_sync(0xFFFFFFFFu, s2, o_);
        }
        float mu  = s * (1.0f / 128.0f);
        float var = s2 * (1.0f / 128.0f) - mu * mu;
        float rstd = rsqrtf(var + 1e-5f);
        if (row < N) {
            float4 o;
            o.x = (v.x - mu) * rstd * gg.x + bev.x;
            o.y = (v.y - mu) * rstd * gg.y + bev.y;
            o.z = (v.z - mu) * rstd * gg.z + bev.z;
            o.w = (v.w - mu) * rstd * gg.w + bev.w;
            *reinterpret_cast<float4*>(&out[(size_t)row * DD + lane * 4]) = o;
        }
    }
}

// ---------------- launch: R12 three-branch DAG (proven schedule) ----------------
extern "C" void kernel_launch(void* const* d_in, const int* in_sizes, int n_in,
                              void* d_out, int out_size)
{
    const float* x_drug  = (const float*)d_in[0];
    const float* x_prot  = (const float*)d_in[1];
    const float* Wagg_dd = (const float*)d_in[2];
    const float* Wagg_dp = (const float*)d_in[3];
    const float* Wagg_pd = (const float*)d_in[4];
    const float* W_drug  = (const float*)d_in[5];
    const float* b_drug  = (const float*)d_in[6];
    const float* W_prot  = (const float*)d_in[7];
    const float* b_prot  = (const float*)d_in[8];
    const float* g_drug  = (const float*)d_in[9];
    const float* be_drug = (const float*)d_in[10];
    const float* g_prot  = (const float*)d_in[11];
    const float* be_prot = (const float*)d_in[12];
    const int* dd_src = (const int*)d_in[13];
    const int* dd_dst = (const int*)d_in[14];
    const int* dp_src = (const int*)d_in[15];
    const int* dp_dst = (const int*)d_in[16];
    const int* pd_src = (const int*)d_in[17];
    const int* pd_dst = (const int*)d_in[18];
    float* out = (float*)d_out;

    __half *Hdd, *Hdp, *Hpd;
    float *Adrug, *Aprot;
    float *WtDD, *WtDP, *WtPD, *WtDR, *WtPR;
    int *off_dd, *off_pd, *off_dp, *esrc_dd, *esrc_pd, *esrc_dp;
    cudaGetSymbolAddress((void**)&Hdd, g_Hdd);
    cudaGetSymbolAddress((void**)&Hdp, g_Hdp);
    cudaGetSymbolAddress((void**)&Hpd, g_Hpd);
    cudaGetSymbolAddress((void**)&Adrug, g_Adrug);
    cudaGetSymbolAddress((void**)&Aprot, g_Aprot);
    cudaGetSymbolAddress((void**)&WtDD, g_WtDD);
    cudaGetSymbolAddress((void**)&WtDP, g_WtDP);
    cudaGetSymbolAddress((void**)&WtPD, g_WtPD);
    cudaGetSymbolAddress((void**)&WtDR, g_WtDR);
    cudaGetSymbolAddress((void**)&WtPR, g_WtPR);
    cudaGetSymbolAddress((void**)&off_dd, g_off_dd);
    cudaGetSymbolAddress((void**)&off_pd, g_off_pd);
    cudaGetSymbolAddress((void**)&off_dp, g_off_dp);
    cudaGetSymbolAddress((void**)&esrc_dd, g_esrc_dd);
    cudaGetSymbolAddress((void**)&esrc_pd, g_esrc_pd);
    cudaGetSymbolAddress((void**)&esrc_dp, g_esrc_dp);

    cudaStream_t s1 = g_res.s1;
    cudaStream_t s2 = g_res.s2;

    // ---- fork s1 off the main stream ----
    cudaEventRecord(g_res.eFork, 0);
    cudaStreamWaitEvent(s1, g_res.eFork, 0);

    // ---- s1: CSR build chain ----
    zero_counts<<<256, 256, 0, s1>>>();
    count_all<<<(EDD + EPD + EDP + 255) / 256, 256, 0, s1>>>(dd_dst, pd_dst, dp_dst);
    chunk_sums<<<NCH_TOT, 1024, 0, s1>>>();
    scan_partials<<<1, 64, 0, s1>>>();
    chunk_scan<<<NCH_TOT, 1024, 0, s1>>>();
    fill_all<<<(EDD + EPD + EDP + 255) / 256, 256, 0, s1>>>(dd_src, dd_dst, pd_src, pd_dst, dp_src, dp_dst);
    cudaEventRecord(g_res.eFill, s1);

    // ---- s0: weight prep + drug/prot aggs ----
    prep_weights<<<256, 256>>>(Wagg_dd, Wagg_dp, Wagg_pd, W_drug, W_prot);
    cudaEventRecord(g_res.ePrep, 0);
    agg_gemm_relu<<<(NDRUG + 63) / 64, 256>>>(x_drug, WtDD, Hdd, NDRUG);
    cudaEventRecord(g_res.eDD, 0);
    agg_gemm_relu<<<(NPROT + 63) / 64, 256>>>(x_prot, WtPD, Hpd, NPROT);
    cudaEventRecord(g_res.ePD, 0);

    // ---- s2: drug->prot branch (independent of node_drug) ----
    cudaStreamWaitEvent(s2, g_res.ePrep, 0);
    agg_gemm_relu<<<(NDRUG + 63) / 64, 256, 0, s2>>>(x_drug, WtDP, Hdp, NDRUG);
    cudaStreamWaitEvent(s2, g_res.eFill, 0);
    gather_prot<<<(NPROT * 32 + 255) / 256, 256, 0, s2>>>(Hdp, esrc_dp, off_dp, Aprot, NPROT);
    node_update<<<(NPROT + 63) / 64, 256, 0, s2>>>(
        x_prot, Aprot, WtPR, b_prot, g_prot, be_prot,
        out + (size_t)NDRUG * DD, NPROT);
    cudaEventRecord(g_res.eEnd2, s2);

    // ---- s1: fused drug gather (needs Hdd + Hpd; ePD covers both, + CSR on s1) ----
    cudaStreamWaitEvent(s1, g_res.ePD, 0);
    gather_drug<<<(NDRUG * 32 + 255) / 256, 256, 0, s1>>>(
        Hdd, Hpd, esrc_dd, off_dd, esrc_pd, off_pd, Adrug, NDRUG);
    cudaEventRecord(g_res.eGD, s1);

    // ---- s0: drug node update, then join ----
    cudaStreamWaitEvent(0, g_res.eGD, 0);
    node_update<<<(NDRUG + 63) / 64, 256>>>(
        x_drug, Adrug, WtDR, b_drug, g_drug, be_drug, out, NDRUG);
    cudaStreamWaitEvent(0, g_res.eEnd2, 0);
}